// round 4
// baseline (speedup 1.0000x reference)
#include <cuda_runtime.h>
#include <cuda_bf16.h>
#include <cstdint>
#include <cstddef>

#define SEQ 128
#define BATCH 64
#define EMB 1024
#define HID 1024
#define OUT_DIM 32000
#define VOCAB 32000
#define KCH 8
#define KC_LEN (HID / KCH)

// HMMA GEMM config: 128x256 block, 64x64 warp tiles, BK=32, 4 stages
#define K2 3072
#define BM 128
#define BN 256
#define BKK 32
#define SROW 80                                   // 64B data + 16B pad
#define STG_BYTES_TC ((BM + BN) * SROW)           // 30720
#define STAGES_TC 4
#define SMEM_TC (STAGES_TC * STG_BYTES_TC)        // 122880
#define NKT2 (K2 / BKK)                           // 96

// ---------------- device scratch ----------------
__device__ __align__(16) float g_xh[SEQ * BATCH * HID];
__device__ __align__(16) float g_h[BATCH * HID];
__device__ __align__(16) float g_part[KCH * BATCH * HID];
__device__ __align__(16) __nv_bfloat16 g_hall2[SEQ * BATCH * K2];     // 48 MB
__device__ __align__(16) __nv_bfloat16 g_wfc2[OUT_DIM * K2];          // 192 MB
__device__ __align__(16) __nv_bfloat16 g_wih2[HID * K2];              // 6 MB
__device__ __align__(16) __nv_bfloat16 g_emb2[SEQ * BATCH * K2];      // 48 MB
__device__ int g_idx[SEQ * BATCH];
__device__ int g_is64;

// ---------------- helpers ----------------
__device__ __forceinline__ uint32_t smem_u32(const void* p) {
    uint32_t a;
    asm("{ .reg .u64 t; cvta.to.shared.u64 t, %1; cvt.u32.u64 %0, t; }" : "=r"(a) : "l"(p));
    return a;
}
__device__ __forceinline__ void cp16(uint32_t s, const void* g) {
    asm volatile("cp.async.cg.shared.global [%0], [%1], 16;" :: "r"(s), "l"(g) : "memory");
}
__device__ __forceinline__ void ldmx4(uint32_t& r0, uint32_t& r1, uint32_t& r2, uint32_t& r3, uint32_t addr) {
    asm volatile("ldmatrix.sync.aligned.m8n8.x4.shared.b16 {%0,%1,%2,%3}, [%4];"
                 : "=r"(r0), "=r"(r1), "=r"(r2), "=r"(r3) : "r"(addr));
}
__device__ __forceinline__ void mma16816(float* c, const uint32_t* a, const uint32_t* b) {
    asm volatile("mma.sync.aligned.m16n8k16.row.col.f32.bf16.bf16.f32 "
                 "{%0,%1,%2,%3}, {%4,%5,%6,%7}, {%8,%9}, {%0,%1,%2,%3};"
                 : "+f"(c[0]), "+f"(c[1]), "+f"(c[2]), "+f"(c[3])
                 : "r"(a[0]), "r"(a[1]), "r"(a[2]), "r"(a[3]), "r"(b[0]), "r"(b[1]));
}

// ---------------- small kernels ----------------
__global__ void k_sniff(const void* x) {
    __shared__ int bad;
    if (threadIdx.x == 0) bad = 0;
    __syncthreads();
    const unsigned long long* p = (const unsigned long long*)x;
    int mybad = 0;
    for (int i = threadIdx.x; i < 4096; i += 256)
        if (p[i] >= (unsigned long long)VOCAB) mybad = 1;
    if (mybad) atomicOr(&bad, 1);
    __syncthreads();
    if (threadIdx.x == 0) g_is64 = bad ? 0 : 1;
}
__global__ void k_decode(const void* x) {
    int i = blockIdx.x * 256 + threadIdx.x;
    if (i >= SEQ * BATCH) return;
    if (g_is64) g_idx[i] = (int)((const long long*)x)[i];
    else        g_idx[i] = ((const int*)x)[i];
}
__global__ void k_copyh(const float* __restrict__ hidden) {
    int i = blockIdx.x * 256 + threadIdx.x;
    if (i < BATCH * HID) g_h[i] = hidden[i];
}
// W [rows x 1024] fp32 -> dst [rows x 3072] bf16 segments [hi | lo | hi]
__global__ void k_convw(const float* __restrict__ W, __nv_bfloat16* __restrict__ dst, int n) {
    int i = blockIdx.x * 256 + threadIdx.x;
    if (i >= n) return;
    float v = W[i];
    __nv_bfloat16 hi = __float2bfloat16(v);
    __nv_bfloat16 lo = __float2bfloat16(v - __bfloat162float(hi));
    int row = i >> 10, k = i & 1023;
    size_t base = (size_t)row * K2 + k;
    dst[base] = hi;
    dst[base + 1024] = lo;
    dst[base + 2048] = hi;
}
// gather emb rows by idx, split to bf16 segments [hi | hi | lo]
__global__ void k_gather_split(const float* __restrict__ emb) {
    int r = blockIdx.x;                 // 0..8191
    int t = threadIdx.x;                // 0..255
    long long src = g_idx[r];
    float4 v = ((const float4*)(emb + (size_t)src * 1024))[t];
    __nv_bfloat16 h0 = __float2bfloat16(v.x), h1 = __float2bfloat16(v.y);
    __nv_bfloat16 h2 = __float2bfloat16(v.z), h3 = __float2bfloat16(v.w);
    __nv_bfloat16 l0 = __float2bfloat16(v.x - __bfloat162float(h0));
    __nv_bfloat16 l1 = __float2bfloat16(v.y - __bfloat162float(h1));
    __nv_bfloat16 l2 = __float2bfloat16(v.z - __bfloat162float(h2));
    __nv_bfloat16 l3 = __float2bfloat16(v.w - __bfloat162float(h3));
    uint2 hp, lp;
    ((__nv_bfloat16*)&hp)[0] = h0; ((__nv_bfloat16*)&hp)[1] = h1;
    ((__nv_bfloat16*)&hp)[2] = h2; ((__nv_bfloat16*)&hp)[3] = h3;
    ((__nv_bfloat16*)&lp)[0] = l0; ((__nv_bfloat16*)&lp)[1] = l1;
    ((__nv_bfloat16*)&lp)[2] = l2; ((__nv_bfloat16*)&lp)[3] = l3;
    __nv_bfloat16* base = g_emb2 + (size_t)r * K2;
    ((uint2*)base)[t] = hp;
    ((uint2*)(base + 1024))[t] = hp;
    ((uint2*)(base + 2048))[t] = lp;
}

// ---------------- fp32 SIMT NT SGEMM (recurrence only) ----------------
__global__ void __launch_bounds__(256)
sgemm_nt64(const float* __restrict__ A, const float* __restrict__ B,
           float* __restrict__ C, int kLen, int cChunkStride, int ldc)
{
    __shared__ __align__(16) float As[32][64];
    __shared__ __align__(16) float Bs[32][64];
    const int t = threadIdx.x;
    const int m0 = blockIdx.y * 64;
    const int n0 = blockIdx.x * 64;
    const int k0 = blockIdx.z * kLen;
    float* Cz = C + (size_t)blockIdx.z * cChunkStride;
    const int lrow = t >> 2;
    const int lkq = (t & 3) * 2;
    const float* Arow = A + (size_t)(m0 + lrow) * 1024 + k0 + lkq * 4;
    const float* Brow = B + (size_t)(n0 + lrow) * 1024 + k0 + lkq * 4;
    const int ty = t >> 4, tx = t & 15;
    float acc[4][4];
#pragma unroll
    for (int i = 0; i < 4; i++)
#pragma unroll
        for (int j = 0; j < 4; j++) acc[i][j] = 0.f;
    for (int kt = 0; kt < kLen; kt += 32) {
        float4 a0 = *(const float4*)(Arow + kt);
        float4 a1 = *(const float4*)(Arow + kt + 4);
        float4 b0 = *(const float4*)(Brow + kt);
        float4 b1 = *(const float4*)(Brow + kt + 4);
        __syncthreads();
        As[lkq * 4 + 0][lrow] = a0.x; As[lkq * 4 + 1][lrow] = a0.y;
        As[lkq * 4 + 2][lrow] = a0.z; As[lkq * 4 + 3][lrow] = a0.w;
        As[lkq * 4 + 4][lrow] = a1.x; As[lkq * 4 + 5][lrow] = a1.y;
        As[lkq * 4 + 6][lrow] = a1.z; As[lkq * 4 + 7][lrow] = a1.w;
        Bs[lkq * 4 + 0][lrow] = b0.x; Bs[lkq * 4 + 1][lrow] = b0.y;
        Bs[lkq * 4 + 2][lrow] = b0.z; Bs[lkq * 4 + 3][lrow] = b0.w;
        Bs[lkq * 4 + 4][lrow] = b1.x; Bs[lkq * 4 + 5][lrow] = b1.y;
        Bs[lkq * 4 + 6][lrow] = b1.z; Bs[lkq * 4 + 7][lrow] = b1.w;
        __syncthreads();
#pragma unroll
        for (int kk = 0; kk < 32; kk++) {
            float4 av = *(const float4*)&As[kk][ty * 4];
            float4 bv = *(const float4*)&Bs[kk][tx * 4];
            float ar[4] = {av.x, av.y, av.z, av.w};
            float br[4] = {bv.x, bv.y, bv.z, bv.w};
#pragma unroll
            for (int i = 0; i < 4; i++)
#pragma unroll
                for (int j = 0; j < 4; j++) acc[i][j] += ar[i] * br[j];
        }
    }
#pragma unroll
    for (int i = 0; i < 4; i++) {
        int m = m0 + ty * 4 + i;
#pragma unroll
        for (int j = 0; j < 4; j++) {
            int n = n0 + tx * 4 + j;
            Cz[(size_t)m * ldc + n] = acc[i][j];
        }
    }
}

// ---------------- recurrence reduce + tanh + bf16 split emit ----------------
__global__ void k_reduce_tanh(int s) {
    int i = blockIdx.x * 256 + threadIdx.x;
    float v = g_xh[(size_t)s * BATCH * HID + i];
#pragma unroll
    for (int kc = 0; kc < KCH; kc++) v += g_part[kc * BATCH * HID + i];
    float h = tanhf(v);
    g_h[i] = h;
    __nv_bfloat16 hi = __float2bfloat16(h);
    __nv_bfloat16 lo = __float2bfloat16(h - __bfloat162float(hi));
    int b = i >> 10, j = i & 1023;
    size_t base = (size_t)(s * BATCH + b) * K2 + j;
    g_hall2[base] = hi;
    g_hall2[base + 1024] = hi;
    g_hall2[base + 2048] = lo;
}

__global__ void k_store_hidden(float* __restrict__ out) {
    int i = blockIdx.x * 256 + threadIdx.x;
    if (i < BATCH * HID) out[i] = g_h[i];
}

// ---------------- HMMA bf16 GEMM: C[M,N] = A2 @ B2^T + bias ----------------
// 128x256 block, 8 warps (2x4), each 64x64. m-fastest block order.
__global__ void __launch_bounds__(256, 1)
gemm_tc(const __nv_bfloat16* __restrict__ A2, const __nv_bfloat16* __restrict__ B2,
        float* __restrict__ C, const float* __restrict__ bias0,
        const float* __restrict__ bias1, int mblocks, int ldc, int nbias)
{
    extern __shared__ __align__(16) char smem[];
    const uint32_t sBase = smem_u32(smem);
    const int t = threadIdx.x;
    const int lane = t & 31, wid = t >> 5;
    const int warp_m = wid & 1;
    const int warp_n = wid >> 1;

    const int m0 = (blockIdx.x % mblocks) * BM;    // m fastest: A L2-resident, B streamed once
    const int n0 = (blockIdx.x / mblocks) * BN;

    // cp.async: 6 x 16B chunks per thread (A: 2, B: 4)
    uint32_t soff[6];
    const char* gptr[6];
#pragma unroll
    for (int i = 0; i < 2; i++) {
        int c = t + 256 * i;                 // 0..511 -> A
        int row = c >> 2, q = c & 3;
        soff[i] = (uint32_t)(row * SROW + q * 16);
        gptr[i] = (const char*)A2 + (size_t)(m0 + row) * (K2 * 2) + q * 16;
    }
#pragma unroll
    for (int i = 0; i < 4; i++) {
        int c = t + 256 * i;                 // 0..1023 -> B
        int row = c >> 2, q = c & 3;
        soff[2 + i] = (uint32_t)(BM * SROW + row * SROW + q * 16);
        gptr[2 + i] = (const char*)B2 + (size_t)(n0 + row) * (K2 * 2) + q * 16;
    }

    // ldmatrix per-lane offsets
    const int arow = ((lane >> 3) & 1) * 8 + (lane & 7);
    const int ahalf = (lane >> 4) & 1;
    const uint32_t aOff = (uint32_t)((warp_m * 64 + arow) * SROW + ahalf * 16);
    const int brow = ((lane >> 4) & 1) * 8 + (lane & 7);
    const int bhalf = (lane >> 3) & 1;
    const uint32_t bOff = (uint32_t)(BM * SROW + (warp_n * 64 + brow) * SROW + bhalf * 16);

    float acc[4][8][4];
#pragma unroll
    for (int mt = 0; mt < 4; mt++)
#pragma unroll
        for (int nt = 0; nt < 8; nt++)
#pragma unroll
            for (int e = 0; e < 4; e++) acc[mt][nt][e] = 0.f;

    // prologue: stages 0..2
#pragma unroll
    for (int p = 0; p < STAGES_TC - 1; p++) {
        uint32_t stg = sBase + p * STG_BYTES_TC;
        size_t koff = (size_t)p * (BKK * 2);
#pragma unroll
        for (int i = 0; i < 6; i++) cp16(stg + soff[i], gptr[i] + koff);
        asm volatile("cp.async.commit_group;" ::: "memory");
    }

    for (int kt = 0; kt < NKT2; kt++) {
        if (kt < NKT2 - 2)      asm volatile("cp.async.wait_group 2;" ::: "memory");
        else if (kt == NKT2 - 2) asm volatile("cp.async.wait_group 1;" ::: "memory");
        else                    asm volatile("cp.async.wait_group 0;" ::: "memory");
        __syncthreads();

        if (kt + 3 < NKT2) {
            uint32_t stg2 = sBase + ((kt + 3) % STAGES_TC) * STG_BYTES_TC;
            size_t koff = (size_t)(kt + 3) * (BKK * 2);
#pragma unroll
            for (int i = 0; i < 6; i++) cp16(stg2 + soff[i], gptr[i] + koff);
            asm volatile("cp.async.commit_group;" ::: "memory");
        }

        const uint32_t stg = sBase + (kt % STAGES_TC) * STG_BYTES_TC;
#pragma unroll
        for (int kp = 0; kp < 2; kp++) {
            uint32_t af[4][4], bf[4][4];
#pragma unroll
            for (int mt = 0; mt < 4; mt++)
                ldmx4(af[mt][0], af[mt][1], af[mt][2], af[mt][3],
                      stg + aOff + mt * 16 * SROW + kp * 32);
#pragma unroll
            for (int p = 0; p < 4; p++)
                ldmx4(bf[p][0], bf[p][1], bf[p][2], bf[p][3],
                      stg + bOff + p * 16 * SROW + kp * 32);
#pragma unroll
            for (int mt = 0; mt < 4; mt++)
#pragma unroll
                for (int nt = 0; nt < 8; nt++)
                    mma16816(acc[mt][nt], af[mt], &bf[nt >> 1][(nt & 1) * 2]);
        }
    }

    // epilogue
#pragma unroll
    for (int mt = 0; mt < 4; mt++) {
        int row = m0 + warp_m * 64 + mt * 16 + (lane >> 2);
#pragma unroll
        for (int nt = 0; nt < 8; nt++) {
            int col = n0 + warp_n * 64 + nt * 8 + (lane & 3) * 2;
            float b0 = 0.f, b1 = 0.f;
            if (nbias >= 1) { b0 += __ldg(&bias0[col]); b1 += __ldg(&bias0[col + 1]); }
            if (nbias >= 2) { b0 += __ldg(&bias1[col]); b1 += __ldg(&bias1[col + 1]); }
            float2 v0 = make_float2(acc[mt][nt][0] + b0, acc[mt][nt][1] + b1);
            float2 v1 = make_float2(acc[mt][nt][2] + b0, acc[mt][nt][3] + b1);
            *(float2*)&C[(size_t)row * ldc + col] = v0;
            *(float2*)&C[(size_t)(row + 8) * ldc + col] = v1;
        }
    }
}

// ---------------- launch ----------------
extern "C" void kernel_launch(void* const* d_in, const int* in_sizes, int n_in,
                              void* d_out, int out_size)
{
    const void*  x      = d_in[0];
    const float* hidden = (const float*)d_in[1];
    const float* emb    = (const float*)d_in[2];
    const float* W_ih   = (const float*)d_in[3];
    const float* W_hh   = (const float*)d_in[4];
    const float* b_ih   = (const float*)d_in[5];
    const float* b_hh   = (const float*)d_in[6];
    const float* W_fc   = (const float*)d_in[7];
    const float* b_fc   = (const float*)d_in[8];
    float* out = (float*)d_out;

    float *p_xh, *p_h, *p_part;
    __nv_bfloat16 *p_hall2, *p_wfc2, *p_wih2, *p_emb2;
    cudaGetSymbolAddress((void**)&p_xh,    g_xh);
    cudaGetSymbolAddress((void**)&p_h,     g_h);
    cudaGetSymbolAddress((void**)&p_part,  g_part);
    cudaGetSymbolAddress((void**)&p_hall2, g_hall2);
    cudaGetSymbolAddress((void**)&p_wfc2,  g_wfc2);
    cudaGetSymbolAddress((void**)&p_wih2,  g_wih2);
    cudaGetSymbolAddress((void**)&p_emb2,  g_emb2);

    cudaFuncSetAttribute(gemm_tc, cudaFuncAttributeMaxDynamicSharedMemorySize, SMEM_TC);

    k_sniff<<<1, 256>>>(x);
    k_decode<<<(SEQ * BATCH + 255) / 256, 256>>>(x);
    k_copyh<<<(BATCH * HID + 255) / 256, 256>>>(hidden);
    k_convw<<<(OUT_DIM * HID) / 256, 256>>>(W_fc, p_wfc2, OUT_DIM * HID);
    k_convw<<<(HID * HID) / 256, 256>>>(W_ih, p_wih2, HID * HID);
    k_gather_split<<<SEQ * BATCH, 256>>>(emb);

    // xh = emb2 @ wih2^T + b_ih + b_hh : M=8192, N=1024
    {
        int mblocks = (SEQ * BATCH) / BM;           // 64
        int nblocks = HID / BN;                     // 4
        gemm_tc<<<mblocks * nblocks, 256, SMEM_TC>>>(
            p_emb2, p_wih2, p_xh, b_ih, b_hh, mblocks, HID, 2);
    }

    // recurrence
    for (int s = 0; s < SEQ; s++) {
        sgemm_nt64<<<dim3(HID / 64, 1, KCH), 256>>>(
            p_h, W_hh, p_part, KC_LEN, BATCH * HID, HID);
        k_reduce_tanh<<<(BATCH * HID) / 256, 256>>>(s);
    }

    // outputs = hall2 @ wfc2^T + b_fc : M=8192, N=32000
    {
        int mblocks = (SEQ * BATCH) / BM;           // 64
        int nblocks = OUT_DIM / BN;                 // 125
        gemm_tc<<<mblocks * nblocks, 256, SMEM_TC>>>(
            p_hall2, p_wfc2, out, b_fc, nullptr, mblocks, OUT_DIM, 1);
    }

    k_store_hidden<<<(BATCH * HID + 255) / 256, 256>>>(out + (size_t)SEQ * BATCH * OUT_DIM);
}

// round 5
// speedup vs baseline: 1.5664x; 1.5664x over previous
#include <cuda_runtime.h>
#include <cuda_bf16.h>
#include <cuda_fp16.h>
#include <cstdint>
#include <cstddef>

#define SEQ 128
#define BATCH 64
#define EMB 1024
#define HID 1024
#define OUT_DIM 32000
#define VOCAB 32000
#define KCH 8
#define KC_LEN (HID / KCH)

// GEMM config: 128x128 block, 4 warps (2x2) of 64x64, BK=32, 4 stages
#define K2 3072                  // bf16 3-term (xh path)
#define KF 2048                  // fp16 2-term (output path, A side)
#define BM 128
#define BN 128
#define BKK 32
#define SROW 80
#define STG_BYTES_TC ((BM + BN) * SROW)          // 20480
#define STAGES_TC 4
#define SMEM_TC (STAGES_TC * STG_BYTES_TC)       // 81920

// ---------------- device scratch ----------------
__device__ __align__(16) float g_xh[SEQ * BATCH * HID];
__device__ __align__(16) float g_h[BATCH * HID];
__device__ __align__(16) float g_part[KCH * BATCH * HID];
__device__ __align__(16) __half g_hallf[SEQ * BATCH * KF];            // 33.5 MB [hi|lo]
__device__ __align__(16) __half g_wfcf[OUT_DIM * HID];                // 64 MB  [hi]
__device__ __align__(16) __nv_bfloat16 g_wih2[HID * K2];              // 6 MB
__device__ __align__(16) __nv_bfloat16 g_emb2[SEQ * BATCH * K2];      // 48 MB
__device__ int g_idx[SEQ * BATCH];
__device__ int g_is64;

// ---------------- helpers ----------------
__device__ __forceinline__ uint32_t smem_u32(const void* p) {
    uint32_t a;
    asm("{ .reg .u64 t; cvta.to.shared.u64 t, %1; cvt.u32.u64 %0, t; }" : "=r"(a) : "l"(p));
    return a;
}
__device__ __forceinline__ void cp16(uint32_t s, const void* g) {
    asm volatile("cp.async.cg.shared.global [%0], [%1], 16;" :: "r"(s), "l"(g) : "memory");
}
__device__ __forceinline__ void ldmx4(uint32_t& r0, uint32_t& r1, uint32_t& r2, uint32_t& r3, uint32_t addr) {
    asm volatile("ldmatrix.sync.aligned.m8n8.x4.shared.b16 {%0,%1,%2,%3}, [%4];"
                 : "=r"(r0), "=r"(r1), "=r"(r2), "=r"(r3) : "r"(addr));
}
__device__ __forceinline__ void mma_bf16(float* c, const uint32_t* a, const uint32_t* b) {
    asm volatile("mma.sync.aligned.m16n8k16.row.col.f32.bf16.bf16.f32 "
                 "{%0,%1,%2,%3}, {%4,%5,%6,%7}, {%8,%9}, {%0,%1,%2,%3};"
                 : "+f"(c[0]), "+f"(c[1]), "+f"(c[2]), "+f"(c[3])
                 : "r"(a[0]), "r"(a[1]), "r"(a[2]), "r"(a[3]), "r"(b[0]), "r"(b[1]));
}
__device__ __forceinline__ void mma_fp16(float* c, const uint32_t* a, const uint32_t* b) {
    asm volatile("mma.sync.aligned.m16n8k16.row.col.f32.f16.f16.f32 "
                 "{%0,%1,%2,%3}, {%4,%5,%6,%7}, {%8,%9}, {%0,%1,%2,%3};"
                 : "+f"(c[0]), "+f"(c[1]), "+f"(c[2]), "+f"(c[3])
                 : "r"(a[0]), "r"(a[1]), "r"(a[2]), "r"(a[3]), "r"(b[0]), "r"(b[1]));
}

// ---------------- small kernels ----------------
__global__ void k_sniff(const void* x) {
    __shared__ int bad;
    if (threadIdx.x == 0) bad = 0;
    __syncthreads();
    const unsigned long long* p = (const unsigned long long*)x;
    int mybad = 0;
    for (int i = threadIdx.x; i < 4096; i += 256)
        if (p[i] >= (unsigned long long)VOCAB) mybad = 1;
    if (mybad) atomicOr(&bad, 1);
    __syncthreads();
    if (threadIdx.x == 0) g_is64 = bad ? 0 : 1;
}
__global__ void k_decode(const void* x) {
    int i = blockIdx.x * 256 + threadIdx.x;
    if (i >= SEQ * BATCH) return;
    if (g_is64) g_idx[i] = (int)((const long long*)x)[i];
    else        g_idx[i] = ((const int*)x)[i];
}
__global__ void k_copyh(const float* __restrict__ hidden) {
    int i = blockIdx.x * 256 + threadIdx.x;
    if (i < BATCH * HID) g_h[i] = hidden[i];
}
// W_ih fp32 [1024x1024] -> bf16 3 segments [hi | lo | hi]
__global__ void k_convw_bf(const float* __restrict__ W) {
    int i = blockIdx.x * 256 + threadIdx.x;
    if (i >= HID * HID) return;
    float v = W[i];
    __nv_bfloat16 hi = __float2bfloat16(v);
    __nv_bfloat16 lo = __float2bfloat16(v - __bfloat162float(hi));
    int row = i >> 10, k = i & 1023;
    size_t base = (size_t)row * K2 + k;
    g_wih2[base] = hi;
    g_wih2[base + 1024] = lo;
    g_wih2[base + 2048] = hi;
}
// W_fc fp32 -> fp16 hi (single copy; GEMM reuses it for both K segments)
__global__ void k_convw_f(const float* __restrict__ W) {
    int i = blockIdx.x * 256 + threadIdx.x;
    if (i < OUT_DIM * HID) g_wfcf[i] = __float2half(W[i]);
}
// gather emb rows, split to bf16 segments [hi | hi | lo]
__global__ void k_gather_split(const float* __restrict__ emb) {
    int r = blockIdx.x;
    int t = threadIdx.x;
    long long src = g_idx[r];
    float4 v = ((const float4*)(emb + (size_t)src * 1024))[t];
    __nv_bfloat16 h0 = __float2bfloat16(v.x), h1 = __float2bfloat16(v.y);
    __nv_bfloat16 h2 = __float2bfloat16(v.z), h3 = __float2bfloat16(v.w);
    __nv_bfloat16 l0 = __float2bfloat16(v.x - __bfloat162float(h0));
    __nv_bfloat16 l1 = __float2bfloat16(v.y - __bfloat162float(h1));
    __nv_bfloat16 l2 = __float2bfloat16(v.z - __bfloat162float(h2));
    __nv_bfloat16 l3 = __float2bfloat16(v.w - __bfloat162float(h3));
    uint2 hp, lp;
    ((__nv_bfloat16*)&hp)[0] = h0; ((__nv_bfloat16*)&hp)[1] = h1;
    ((__nv_bfloat16*)&hp)[2] = h2; ((__nv_bfloat16*)&hp)[3] = h3;
    ((__nv_bfloat16*)&lp)[0] = l0; ((__nv_bfloat16*)&lp)[1] = l1;
    ((__nv_bfloat16*)&lp)[2] = l2; ((__nv_bfloat16*)&lp)[3] = l3;
    __nv_bfloat16* base = g_emb2 + (size_t)r * K2;
    ((uint2*)base)[t] = hp;
    ((uint2*)(base + 1024))[t] = hp;
    ((uint2*)(base + 2048))[t] = lp;
}

// ---------------- fp32 SIMT NT SGEMM (recurrence) ----------------
__global__ void __launch_bounds__(256)
sgemm_nt64(const float* __restrict__ A, const float* __restrict__ B,
           float* __restrict__ C, int kLen, int cChunkStride, int ldc)
{
    __shared__ __align__(16) float As[32][64];
    __shared__ __align__(16) float Bs[32][64];
    const int t = threadIdx.x;
    const int m0 = blockIdx.y * 64;
    const int n0 = blockIdx.x * 64;
    const int k0 = blockIdx.z * kLen;
    float* Cz = C + (size_t)blockIdx.z * cChunkStride;
    const int lrow = t >> 2;
    const int lkq = (t & 3) * 2;
    const float* Arow = A + (size_t)(m0 + lrow) * 1024 + k0 + lkq * 4;
    const float* Brow = B + (size_t)(n0 + lrow) * 1024 + k0 + lkq * 4;
    const int ty = t >> 4, tx = t & 15;
    float acc[4][4];
#pragma unroll
    for (int i = 0; i < 4; i++)
#pragma unroll
        for (int j = 0; j < 4; j++) acc[i][j] = 0.f;
    for (int kt = 0; kt < kLen; kt += 32) {
        float4 a0 = *(const float4*)(Arow + kt);
        float4 a1 = *(const float4*)(Arow + kt + 4);
        float4 b0 = *(const float4*)(Brow + kt);
        float4 b1 = *(const float4*)(Brow + kt + 4);
        __syncthreads();
        As[lkq * 4 + 0][lrow] = a0.x; As[lkq * 4 + 1][lrow] = a0.y;
        As[lkq * 4 + 2][lrow] = a0.z; As[lkq * 4 + 3][lrow] = a0.w;
        As[lkq * 4 + 4][lrow] = a1.x; As[lkq * 4 + 5][lrow] = a1.y;
        As[lkq * 4 + 6][lrow] = a1.z; As[lkq * 4 + 7][lrow] = a1.w;
        Bs[lkq * 4 + 0][lrow] = b0.x; Bs[lkq * 4 + 1][lrow] = b0.y;
        Bs[lkq * 4 + 2][lrow] = b0.z; Bs[lkq * 4 + 3][lrow] = b0.w;
        Bs[lkq * 4 + 4][lrow] = b1.x; Bs[lkq * 4 + 5][lrow] = b1.y;
        Bs[lkq * 4 + 6][lrow] = b1.z; Bs[lkq * 4 + 7][lrow] = b1.w;
        __syncthreads();
#pragma unroll
        for (int kk = 0; kk < 32; kk++) {
            float4 av = *(const float4*)&As[kk][ty * 4];
            float4 bv = *(const float4*)&Bs[kk][tx * 4];
            float ar[4] = {av.x, av.y, av.z, av.w};
            float br[4] = {bv.x, bv.y, bv.z, bv.w};
#pragma unroll
            for (int i = 0; i < 4; i++)
#pragma unroll
                for (int j = 0; j < 4; j++) acc[i][j] += ar[i] * br[j];
        }
    }
#pragma unroll
    for (int i = 0; i < 4; i++) {
        int m = m0 + ty * 4 + i;
#pragma unroll
        for (int j = 0; j < 4; j++)
            Cz[(size_t)m * ldc + n0 + tx * 4 + j] = acc[i][j];
    }
}

// ---------------- recurrence reduce + tanh + fp16 split emit ----------------
__global__ void k_reduce_tanh(int s) {
    int i = blockIdx.x * 256 + threadIdx.x;
    float v = g_xh[(size_t)s * BATCH * HID + i];
#pragma unroll
    for (int kc = 0; kc < KCH; kc++) v += g_part[kc * BATCH * HID + i];
    float h = tanhf(v);
    g_h[i] = h;
    __half hi = __float2half(h);
    __half lo = __float2half(h - __half2float(hi));
    int b = i >> 10, j = i & 1023;
    size_t base = (size_t)(s * BATCH + b) * KF + j;
    g_hallf[base] = hi;
    g_hallf[base + 1024] = lo;
}

__global__ void k_store_hidden(float* __restrict__ out) {
    int i = blockIdx.x * 256 + threadIdx.x;
    if (i < BATCH * HID) out[i] = g_h[i];
}

// ---------------- HMMA GEMM: C[M,N] = A @ B^T + bias ----------------
// 128x128 block, 4 warps (2x2) of 64x64. m-fastest block order.
// B k-offset wraps with bkmask (reuse a single stored B segment).
template<bool FP16>
__global__ void __launch_bounds__(128, 2)
gemm_tc(const char* __restrict__ A2, const char* __restrict__ B2,
        float* __restrict__ C, const float* __restrict__ bias0,
        const float* __restrict__ bias1, int mblocks, int ldc, int nbias,
        int kaElems, int kbElems, int nkt, int bkmask)
{
    extern __shared__ __align__(16) char smem[];
    const uint32_t sBase = smem_u32(smem);
    const int t = threadIdx.x;
    const int lane = t & 31, wid = t >> 5;
    const int warp_m = wid & 1;
    const int warp_n = wid >> 1;

    const int m0 = (blockIdx.x % mblocks) * BM;
    const int n0 = (blockIdx.x / mblocks) * BN;

    // cp.async: 4 A-chunks + 4 B-chunks of 16B per thread (128 threads)
    uint32_t soffA[4], soffB[4];
    const char *gA[4], *gB[4];
#pragma unroll
    for (int i = 0; i < 4; i++) {
        int c = t + 128 * i;              // 0..511
        int row = c >> 2, q = c & 3;
        soffA[i] = (uint32_t)(row * SROW + q * 16);
        soffB[i] = (uint32_t)(BM * SROW + row * SROW + q * 16);
        gA[i] = A2 + ((size_t)(m0 + row) * kaElems + q * 8) * 2;
        gB[i] = B2 + ((size_t)(n0 + row) * kbElems + q * 8) * 2;
    }

    const int arow = ((lane >> 3) & 1) * 8 + (lane & 7);
    const int ahalf = (lane >> 4) & 1;
    const uint32_t aOff = (uint32_t)((warp_m * 64 + arow) * SROW + ahalf * 16);
    const int brow = ((lane >> 4) & 1) * 8 + (lane & 7);
    const int bhalf = (lane >> 3) & 1;
    const uint32_t bOff = (uint32_t)(BM * SROW + (warp_n * 64 + brow) * SROW + bhalf * 16);

    float acc[4][8][4];
#pragma unroll
    for (int mt = 0; mt < 4; mt++)
#pragma unroll
        for (int nt = 0; nt < 8; nt++)
#pragma unroll
            for (int e = 0; e < 4; e++) acc[mt][nt][e] = 0.f;

#pragma unroll
    for (int p = 0; p < STAGES_TC - 1; p++) {
        uint32_t stg = sBase + p * STG_BYTES_TC;
        size_t ka = (size_t)p * 64;
        size_t kb = (size_t)(p & bkmask) * 64;
#pragma unroll
        for (int i = 0; i < 4; i++) cp16(stg + soffA[i], gA[i] + ka);
#pragma unroll
        for (int i = 0; i < 4; i++) cp16(stg + soffB[i], gB[i] + kb);
        asm volatile("cp.async.commit_group;" ::: "memory");
    }

    for (int kt = 0; kt < nkt; kt++) {
        if (kt < nkt - 2)       asm volatile("cp.async.wait_group 2;" ::: "memory");
        else if (kt == nkt - 2) asm volatile("cp.async.wait_group 1;" ::: "memory");
        else                    asm volatile("cp.async.wait_group 0;" ::: "memory");
        __syncthreads();

        if (kt + 3 < nkt) {
            uint32_t stg2 = sBase + ((kt + 3) & 3) * STG_BYTES_TC;
            size_t ka = (size_t)(kt + 3) * 64;
            size_t kb = (size_t)((kt + 3) & bkmask) * 64;
#pragma unroll
            for (int i = 0; i < 4; i++) cp16(stg2 + soffA[i], gA[i] + ka);
#pragma unroll
            for (int i = 0; i < 4; i++) cp16(stg2 + soffB[i], gB[i] + kb);
            asm volatile("cp.async.commit_group;" ::: "memory");
        }

        const uint32_t stg = sBase + (kt & 3) * STG_BYTES_TC;
#pragma unroll
        for (int kp = 0; kp < 2; kp++) {
            uint32_t af[4][4], bf[4][4];
#pragma unroll
            for (int mt = 0; mt < 4; mt++)
                ldmx4(af[mt][0], af[mt][1], af[mt][2], af[mt][3],
                      stg + aOff + mt * 16 * SROW + kp * 32);
#pragma unroll
            for (int p = 0; p < 4; p++)
                ldmx4(bf[p][0], bf[p][1], bf[p][2], bf[p][3],
                      stg + bOff + p * 16 * SROW + kp * 32);
#pragma unroll
            for (int mt = 0; mt < 4; mt++)
#pragma unroll
                for (int nt = 0; nt < 8; nt++) {
                    if (FP16) mma_fp16(acc[mt][nt], af[mt], &bf[nt >> 1][(nt & 1) * 2]);
                    else      mma_bf16(acc[mt][nt], af[mt], &bf[nt >> 1][(nt & 1) * 2]);
                }
        }
    }

#pragma unroll
    for (int mt = 0; mt < 4; mt++) {
        int row = m0 + warp_m * 64 + mt * 16 + (lane >> 2);
#pragma unroll
        for (int nt = 0; nt < 8; nt++) {
            int col = n0 + warp_n * 64 + nt * 8 + (lane & 3) * 2;
            float b0 = 0.f, b1 = 0.f;
            if (nbias >= 1) { b0 += __ldg(&bias0[col]); b1 += __ldg(&bias0[col + 1]); }
            if (nbias >= 2) { b0 += __ldg(&bias1[col]); b1 += __ldg(&bias1[col + 1]); }
            float2 v0 = make_float2(acc[mt][nt][0] + b0, acc[mt][nt][1] + b1);
            float2 v1 = make_float2(acc[mt][nt][2] + b0, acc[mt][nt][3] + b1);
            *(float2*)&C[(size_t)row * ldc + col] = v0;
            *(float2*)&C[(size_t)(row + 8) * ldc + col] = v1;
        }
    }
}

// ---------------- launch ----------------
extern "C" void kernel_launch(void* const* d_in, const int* in_sizes, int n_in,
                              void* d_out, int out_size)
{
    const void*  x      = d_in[0];
    const float* hidden = (const float*)d_in[1];
    const float* emb    = (const float*)d_in[2];
    const float* W_ih   = (const float*)d_in[3];
    const float* W_hh   = (const float*)d_in[4];
    const float* b_ih   = (const float*)d_in[5];
    const float* b_hh   = (const float*)d_in[6];
    const float* W_fc   = (const float*)d_in[7];
    const float* b_fc   = (const float*)d_in[8];
    float* out = (float*)d_out;

    float *p_xh, *p_h, *p_part;
    void *p_hallf, *p_wfcf, *p_wih2, *p_emb2;
    cudaGetSymbolAddress((void**)&p_xh,    g_xh);
    cudaGetSymbolAddress((void**)&p_h,     g_h);
    cudaGetSymbolAddress((void**)&p_part,  g_part);
    cudaGetSymbolAddress(&p_hallf, g_hallf);
    cudaGetSymbolAddress(&p_wfcf,  g_wfcf);
    cudaGetSymbolAddress(&p_wih2,  g_wih2);
    cudaGetSymbolAddress(&p_emb2,  g_emb2);

    cudaFuncSetAttribute(gemm_tc<true>,  cudaFuncAttributeMaxDynamicSharedMemorySize, SMEM_TC);
    cudaFuncSetAttribute(gemm_tc<false>, cudaFuncAttributeMaxDynamicSharedMemorySize, SMEM_TC);

    k_sniff<<<1, 256>>>(x);
    k_decode<<<(SEQ * BATCH + 255) / 256, 256>>>(x);
    k_copyh<<<(BATCH * HID + 255) / 256, 256>>>(hidden);
    k_convw_bf<<<(HID * HID) / 256, 256>>>(W_ih);
    k_convw_f<<<(OUT_DIM * HID) / 256, 256>>>(W_fc);
    k_gather_split<<<SEQ * BATCH, 256>>>(emb);

    // xh = emb2 @ wih2^T + b_ih + b_hh : bf16 3-term, M=8192, N=1024
    {
        int mblocks = (SEQ * BATCH) / BM;   // 64
        int nblocks = HID / BN;             // 8
        gemm_tc<false><<<mblocks * nblocks, 128, SMEM_TC>>>(
            (const char*)p_emb2, (const char*)p_wih2, p_xh, b_ih, b_hh,
            mblocks, HID, 2, K2, K2, K2 / BKK, 0xFF);
    }

    // recurrence
    for (int s = 0; s < SEQ; s++) {
        sgemm_nt64<<<dim3(HID / 64, 1, KCH), 256>>>(
            p_h, W_hh, p_part, KC_LEN, BATCH * HID, HID);
        k_reduce_tanh<<<(BATCH * HID) / 256, 256>>>(s);
    }

    // outputs = hallf @ wfcf^T + b_fc : fp16 2-term (B wraps), M=8192, N=32000
    {
        int mblocks = (SEQ * BATCH) / BM;   // 64
        int nblocks = OUT_DIM / BN;         // 250
        gemm_tc<true><<<mblocks * nblocks, 128, SMEM_TC>>>(
            (const char*)p_hallf, (const char*)p_wfcf, out, b_fc, nullptr,
            mblocks, OUT_DIM, 1, KF, HID, KF / BKK, 31);
    }

    k_store_hidden<<<(BATCH * HID + 255) / 256, 256>>>(out + (size_t)SEQ * BATCH * OUT_DIM);
}

// round 6
// speedup vs baseline: 2.1800x; 1.3917x over previous
#include <cuda_runtime.h>
#include <cuda_bf16.h>
#include <cuda_fp16.h>
#include <cstdint>
#include <cstddef>

#define SEQ 128
#define BATCH 64
#define EMB 1024
#define HID 1024
#define OUT_DIM 32000
#define VOCAB 32000
#define KCH 8
#define KC_LEN (HID / KCH)
#define RNN_BLOCKS 128

// GEMM config: 128x128 block, 4 warps (2x2) of 64x64, BK=32, 4 stages
#define K2 3072                  // bf16 3-term (xh path)
#define KF1 1024                 // fp16 1-term (output path)
#define BM 128
#define BN 128
#define BKK 32
#define SROW 80
#define STG_BYTES_TC ((BM + BN) * SROW)          // 20480
#define STAGES_TC 4
#define SMEM_TC (STAGES_TC * STG_BYTES_TC)       // 81920

// ---------------- device scratch ----------------
__device__ __align__(16) float g_xh[SEQ * BATCH * HID];
__device__ __align__(16) float g_h[BATCH * HID];
__device__ __align__(16) float g_part[KCH * BATCH * HID];
__device__ __align__(16) __half g_hallf[SEQ * BATCH * KF1];           // 16.8 MB [hi]
__device__ __align__(16) __half g_wfcf[OUT_DIM * HID];                // 64 MB  [hi]
__device__ __align__(16) __nv_bfloat16 g_wih2[HID * K2];              // 6 MB
__device__ __align__(16) __nv_bfloat16 g_emb2[SEQ * BATCH * K2];      // 48 MB
__device__ int g_idx[SEQ * BATCH];
__device__ int g_is64;
__device__ unsigned g_arrive;

// ---------------- helpers ----------------
__device__ __forceinline__ uint32_t smem_u32(const void* p) {
    uint32_t a;
    asm("{ .reg .u64 t; cvta.to.shared.u64 t, %1; cvt.u32.u64 %0, t; }" : "=r"(a) : "l"(p));
    return a;
}
__device__ __forceinline__ void cp16(uint32_t s, const void* g) {
    asm volatile("cp.async.cg.shared.global [%0], [%1], 16;" :: "r"(s), "l"(g) : "memory");
}
__device__ __forceinline__ void ldmx4(uint32_t& r0, uint32_t& r1, uint32_t& r2, uint32_t& r3, uint32_t addr) {
    asm volatile("ldmatrix.sync.aligned.m8n8.x4.shared.b16 {%0,%1,%2,%3}, [%4];"
                 : "=r"(r0), "=r"(r1), "=r"(r2), "=r"(r3) : "r"(addr));
}
__device__ __forceinline__ void mma_bf16(float* c, const uint32_t* a, const uint32_t* b) {
    asm volatile("mma.sync.aligned.m16n8k16.row.col.f32.bf16.bf16.f32 "
                 "{%0,%1,%2,%3}, {%4,%5,%6,%7}, {%8,%9}, {%0,%1,%2,%3};"
                 : "+f"(c[0]), "+f"(c[1]), "+f"(c[2]), "+f"(c[3])
                 : "r"(a[0]), "r"(a[1]), "r"(a[2]), "r"(a[3]), "r"(b[0]), "r"(b[1]));
}
__device__ __forceinline__ void mma_fp16(float* c, const uint32_t* a, const uint32_t* b) {
    asm volatile("mma.sync.aligned.m16n8k16.row.col.f32.f16.f16.f32 "
                 "{%0,%1,%2,%3}, {%4,%5,%6,%7}, {%8,%9}, {%0,%1,%2,%3};"
                 : "+f"(c[0]), "+f"(c[1]), "+f"(c[2]), "+f"(c[3])
                 : "r"(a[0]), "r"(a[1]), "r"(a[2]), "r"(a[3]), "r"(b[0]), "r"(b[1]));
}
// grid sync: monotonic counter, phase target supplied by caller
__device__ __forceinline__ void gsync(unsigned target) {
    __syncthreads();
    if (threadIdx.x == 0) {
        __threadfence();
        atomicAdd(&g_arrive, 1u);
        while (*((volatile unsigned*)&g_arrive) < target) { }
        __threadfence();
    }
    __syncthreads();
}

// ---------------- small kernels ----------------
__global__ void k_sniff(const void* x) {
    __shared__ int bad;
    if (threadIdx.x == 0) bad = 0;
    __syncthreads();
    const unsigned long long* p = (const unsigned long long*)x;
    int mybad = 0;
    for (int i = threadIdx.x; i < 4096; i += 256)
        if (p[i] >= (unsigned long long)VOCAB) mybad = 1;
    if (mybad) atomicOr(&bad, 1);
    __syncthreads();
    if (threadIdx.x == 0) g_is64 = bad ? 0 : 1;
}
__global__ void k_decode(const void* x) {
    int i = blockIdx.x * 256 + threadIdx.x;
    if (i >= SEQ * BATCH) return;
    if (g_is64) g_idx[i] = (int)((const long long*)x)[i];
    else        g_idx[i] = ((const int*)x)[i];
}
__global__ void k_copyh(const float* __restrict__ hidden) {
    int i = blockIdx.x * 256 + threadIdx.x;
    if (i == 0) g_arrive = 0;                  // reset grid-sync counter every launch
    if (i < BATCH * HID) g_h[i] = hidden[i];
}
// W_ih fp32 -> bf16 3 segments [hi | lo | hi]
__global__ void k_convw_bf(const float* __restrict__ W) {
    int i = blockIdx.x * 256 + threadIdx.x;
    if (i >= HID * HID) return;
    float v = W[i];
    __nv_bfloat16 hi = __float2bfloat16(v);
    __nv_bfloat16 lo = __float2bfloat16(v - __bfloat162float(hi));
    int row = i >> 10, k = i & 1023;
    size_t base = (size_t)row * K2 + k;
    g_wih2[base] = hi;
    g_wih2[base + 1024] = lo;
    g_wih2[base + 2048] = hi;
}
// W_fc fp32 -> fp16
__global__ void k_convw_f(const float* __restrict__ W) {
    int i = blockIdx.x * 256 + threadIdx.x;
    if (i < OUT_DIM * HID) g_wfcf[i] = __float2half(W[i]);
}
// gather emb rows, split to bf16 segments [hi | hi | lo]
__global__ void k_gather_split(const float* __restrict__ emb) {
    int r = blockIdx.x;
    int t = threadIdx.x;
    long long src = g_idx[r];
    float4 v = ((const float4*)(emb + (size_t)src * 1024))[t];
    __nv_bfloat16 h0 = __float2bfloat16(v.x), h1 = __float2bfloat16(v.y);
    __nv_bfloat16 h2 = __float2bfloat16(v.z), h3 = __float2bfloat16(v.w);
    __nv_bfloat16 l0 = __float2bfloat16(v.x - __bfloat162float(h0));
    __nv_bfloat16 l1 = __float2bfloat16(v.y - __bfloat162float(h1));
    __nv_bfloat16 l2 = __float2bfloat16(v.z - __bfloat162float(h2));
    __nv_bfloat16 l3 = __float2bfloat16(v.w - __bfloat162float(h3));
    uint2 hp, lp;
    ((__nv_bfloat16*)&hp)[0] = h0; ((__nv_bfloat16*)&hp)[1] = h1;
    ((__nv_bfloat16*)&hp)[2] = h2; ((__nv_bfloat16*)&hp)[3] = h3;
    ((__nv_bfloat16*)&lp)[0] = l0; ((__nv_bfloat16*)&lp)[1] = l1;
    ((__nv_bfloat16*)&lp)[2] = l2; ((__nv_bfloat16*)&lp)[3] = l3;
    __nv_bfloat16* base = g_emb2 + (size_t)r * K2;
    ((uint2*)base)[t] = hp;
    ((uint2*)(base + 1024))[t] = hp;
    ((uint2*)(base + 2048))[t] = lp;
}

// ---------------- persistent recurrence kernel ----------------
// 128 blocks x 256 threads, 1 CTA/SM guaranteed resident (no deadlock).
// Per step: phase A = split-K partial GEMM (16 n-tiles x 8 k-chunks),
//           phase B = reduce + tanh + fp16 emit. DIY grid sync between.
// All cross-block traffic uses L1-bypass (__ldcg/__stcg) since there are no
// launch-boundary L1 flushes inside the loop.
__global__ void __launch_bounds__(256) k_rnn_persist(const float* __restrict__ Whh) {
    __shared__ __align__(16) float As[32][64];
    __shared__ __align__(16) float Bs[32][64];
    const int t = threadIdx.x;
    const int bid = blockIdx.x;
    const int nx = bid & 15;              // n-tile (64 cols)
    const int kz = bid >> 4;              // k-chunk (128 k)
    const int n0 = nx * 64;
    const int k0 = kz * KC_LEN;
    const int lrow = t >> 2;
    const int lkq = (t & 3) * 2;
    const int ty = t >> 4, tx = t & 15;
    const float* Brow = Whh + (size_t)(n0 + lrow) * 1024 + k0 + lkq * 4;
    const float* Arow0 = g_h + (size_t)lrow * 1024 + k0 + lkq * 4;
    float* partBase = g_part + (size_t)kz * (BATCH * HID);
    const int i0 = bid * 512 + t;         // phase-B element base (2 per thread)

    unsigned target = 0;
    for (int s = 0; s < SEQ; s++) {
        // ---- phase A ----
        float acc[4][4];
#pragma unroll
        for (int i = 0; i < 4; i++)
#pragma unroll
            for (int j = 0; j < 4; j++) acc[i][j] = 0.f;
#pragma unroll
        for (int kt = 0; kt < KC_LEN; kt += 32) {
            float4 a0 = __ldcg((const float4*)(Arow0 + kt));
            float4 a1 = __ldcg((const float4*)(Arow0 + kt + 4));
            float4 b0 = *(const float4*)(Brow + kt);
            float4 b1 = *(const float4*)(Brow + kt + 4);
            __syncthreads();
            As[lkq * 4 + 0][lrow] = a0.x; As[lkq * 4 + 1][lrow] = a0.y;
            As[lkq * 4 + 2][lrow] = a0.z; As[lkq * 4 + 3][lrow] = a0.w;
            As[lkq * 4 + 4][lrow] = a1.x; As[lkq * 4 + 5][lrow] = a1.y;
            As[lkq * 4 + 6][lrow] = a1.z; As[lkq * 4 + 7][lrow] = a1.w;
            Bs[lkq * 4 + 0][lrow] = b0.x; Bs[lkq * 4 + 1][lrow] = b0.y;
            Bs[lkq * 4 + 2][lrow] = b0.z; Bs[lkq * 4 + 3][lrow] = b0.w;
            Bs[lkq * 4 + 4][lrow] = b1.x; Bs[lkq * 4 + 5][lrow] = b1.y;
            Bs[lkq * 4 + 6][lrow] = b1.z; Bs[lkq * 4 + 7][lrow] = b1.w;
            __syncthreads();
#pragma unroll
            for (int kk = 0; kk < 32; kk++) {
                float4 av = *(const float4*)&As[kk][ty * 4];
                float4 bv = *(const float4*)&Bs[kk][tx * 4];
                float ar[4] = {av.x, av.y, av.z, av.w};
                float br[4] = {bv.x, bv.y, bv.z, bv.w};
#pragma unroll
                for (int i = 0; i < 4; i++)
#pragma unroll
                    for (int j = 0; j < 4; j++) acc[i][j] += ar[i] * br[j];
            }
        }
#pragma unroll
        for (int i = 0; i < 4; i++)
#pragma unroll
            for (int j = 0; j < 4; j++)
                __stcg(&partBase[(size_t)(ty * 4 + i) * 1024 + n0 + tx * 4 + j], acc[i][j]);

        target += RNN_BLOCKS;
        gsync(target);

        // ---- phase B ----
        const float* xh_s = g_xh + (size_t)s * (BATCH * HID);
#pragma unroll
        for (int e = 0; e < 2; e++) {
            int i = i0 + e * 256;
            float v = xh_s[i];
#pragma unroll
            for (int kc = 0; kc < KCH; kc++) v += __ldcg(&g_part[(size_t)kc * (BATCH * HID) + i]);
            float h = tanhf(v);
            __stcg(&g_h[i], h);
            int b = i >> 10, j = i & 1023;
            g_hallf[(size_t)(s * BATCH + b) * KF1 + j] = __float2half(h);
        }

        target += RNN_BLOCKS;
        gsync(target);
    }
}

__global__ void k_store_hidden(float* __restrict__ out) {
    int i = blockIdx.x * 256 + threadIdx.x;
    if (i < BATCH * HID) out[i] = g_h[i];
}

// ---------------- HMMA GEMM: C[M,N] = A @ B^T + bias ----------------
// 128x128 block, 4 warps (2x2) of 64x64. m-fastest block order.
template<bool FP16>
__global__ void __launch_bounds__(128, 2)
gemm_tc(const char* __restrict__ A2, const char* __restrict__ B2,
        float* __restrict__ C, const float* __restrict__ bias0,
        const float* __restrict__ bias1, int mblocks, int ldc, int nbias,
        int kaElems, int kbElems, int nkt)
{
    extern __shared__ __align__(16) char smem[];
    const uint32_t sBase = smem_u32(smem);
    const int t = threadIdx.x;
    const int lane = t & 31, wid = t >> 5;
    const int warp_m = wid & 1;
    const int warp_n = wid >> 1;

    const int m0 = (blockIdx.x % mblocks) * BM;
    const int n0 = (blockIdx.x / mblocks) * BN;

    uint32_t soffA[4], soffB[4];
    const char *gA[4], *gB[4];
#pragma unroll
    for (int i = 0; i < 4; i++) {
        int c = t + 128 * i;
        int row = c >> 2, q = c & 3;
        soffA[i] = (uint32_t)(row * SROW + q * 16);
        soffB[i] = (uint32_t)(BM * SROW + row * SROW + q * 16);
        gA[i] = A2 + ((size_t)(m0 + row) * kaElems + q * 8) * 2;
        gB[i] = B2 + ((size_t)(n0 + row) * kbElems + q * 8) * 2;
    }

    const int arow = ((lane >> 3) & 1) * 8 + (lane & 7);
    const int ahalf = (lane >> 4) & 1;
    const uint32_t aOff = (uint32_t)((warp_m * 64 + arow) * SROW + ahalf * 16);
    const int brow = ((lane >> 4) & 1) * 8 + (lane & 7);
    const int bhalf = (lane >> 3) & 1;
    const uint32_t bOff = (uint32_t)(BM * SROW + (warp_n * 64 + brow) * SROW + bhalf * 16);

    float acc[4][8][4];
#pragma unroll
    for (int mt = 0; mt < 4; mt++)
#pragma unroll
        for (int nt = 0; nt < 8; nt++)
#pragma unroll
            for (int e = 0; e < 4; e++) acc[mt][nt][e] = 0.f;

#pragma unroll
    for (int p = 0; p < STAGES_TC - 1; p++) {
        uint32_t stg = sBase + p * STG_BYTES_TC;
        size_t ko = (size_t)p * 64;
#pragma unroll
        for (int i = 0; i < 4; i++) cp16(stg + soffA[i], gA[i] + ko);
#pragma unroll
        for (int i = 0; i < 4; i++) cp16(stg + soffB[i], gB[i] + ko);
        asm volatile("cp.async.commit_group;" ::: "memory");
    }

    for (int kt = 0; kt < nkt; kt++) {
        if (kt < nkt - 2)       asm volatile("cp.async.wait_group 2;" ::: "memory");
        else if (kt == nkt - 2) asm volatile("cp.async.wait_group 1;" ::: "memory");
        else                    asm volatile("cp.async.wait_group 0;" ::: "memory");
        __syncthreads();

        if (kt + 3 < nkt) {
            uint32_t stg2 = sBase + ((kt + 3) & 3) * STG_BYTES_TC;
            size_t ko = (size_t)(kt + 3) * 64;
#pragma unroll
            for (int i = 0; i < 4; i++) cp16(stg2 + soffA[i], gA[i] + ko);
#pragma unroll
            for (int i = 0; i < 4; i++) cp16(stg2 + soffB[i], gB[i] + ko);
            asm volatile("cp.async.commit_group;" ::: "memory");
        }

        const uint32_t stg = sBase + (kt & 3) * STG_BYTES_TC;
#pragma unroll
        for (int kp = 0; kp < 2; kp++) {
            uint32_t af[4][4], bf[4][4];
#pragma unroll
            for (int mt = 0; mt < 4; mt++)
                ldmx4(af[mt][0], af[mt][1], af[mt][2], af[mt][3],
                      stg + aOff + mt * 16 * SROW + kp * 32);
#pragma unroll
            for (int p = 0; p < 4; p++)
                ldmx4(bf[p][0], bf[p][1], bf[p][2], bf[p][3],
                      stg + bOff + p * 16 * SROW + kp * 32);
#pragma unroll
            for (int mt = 0; mt < 4; mt++)
#pragma unroll
                for (int nt = 0; nt < 8; nt++) {
                    if (FP16) mma_fp16(acc[mt][nt], af[mt], &bf[nt >> 1][(nt & 1) * 2]);
                    else      mma_bf16(acc[mt][nt], af[mt], &bf[nt >> 1][(nt & 1) * 2]);
                }
        }
    }

#pragma unroll
    for (int mt = 0; mt < 4; mt++) {
        int row = m0 + warp_m * 64 + mt * 16 + (lane >> 2);
#pragma unroll
        for (int nt = 0; nt < 8; nt++) {
            int col = n0 + warp_n * 64 + nt * 8 + (lane & 3) * 2;
            float b0 = 0.f, b1 = 0.f;
            if (nbias >= 1) { b0 += __ldg(&bias0[col]); b1 += __ldg(&bias0[col + 1]); }
            if (nbias >= 2) { b0 += __ldg(&bias1[col]); b1 += __ldg(&bias1[col + 1]); }
            float2 v0 = make_float2(acc[mt][nt][0] + b0, acc[mt][nt][1] + b1);
            float2 v1 = make_float2(acc[mt][nt][2] + b0, acc[mt][nt][3] + b1);
            *(float2*)&C[(size_t)row * ldc + col] = v0;
            *(float2*)&C[(size_t)(row + 8) * ldc + col] = v1;
        }
    }
}

// ---------------- launch ----------------
extern "C" void kernel_launch(void* const* d_in, const int* in_sizes, int n_in,
                              void* d_out, int out_size)
{
    const void*  x      = d_in[0];
    const float* hidden = (const float*)d_in[1];
    const float* emb    = (const float*)d_in[2];
    const float* W_ih   = (const float*)d_in[3];
    const float* W_hh   = (const float*)d_in[4];
    const float* b_ih   = (const float*)d_in[5];
    const float* b_hh   = (const float*)d_in[6];
    const float* W_fc   = (const float*)d_in[7];
    const float* b_fc   = (const float*)d_in[8];
    float* out = (float*)d_out;

    float* p_xh;
    void *p_hallf, *p_wfcf, *p_wih2, *p_emb2;
    cudaGetSymbolAddress((void**)&p_xh, g_xh);
    cudaGetSymbolAddress(&p_hallf, g_hallf);
    cudaGetSymbolAddress(&p_wfcf,  g_wfcf);
    cudaGetSymbolAddress(&p_wih2,  g_wih2);
    cudaGetSymbolAddress(&p_emb2,  g_emb2);

    cudaFuncSetAttribute(gemm_tc<true>,  cudaFuncAttributeMaxDynamicSharedMemorySize, SMEM_TC);
    cudaFuncSetAttribute(gemm_tc<false>, cudaFuncAttributeMaxDynamicSharedMemorySize, SMEM_TC);

    k_sniff<<<1, 256>>>(x);
    k_decode<<<(SEQ * BATCH + 255) / 256, 256>>>(x);
    k_copyh<<<(BATCH * HID + 255) / 256, 256>>>(hidden);
    k_convw_bf<<<(HID * HID) / 256, 256>>>(W_ih);
    k_convw_f<<<(OUT_DIM * HID) / 256, 256>>>(W_fc);
    k_gather_split<<<SEQ * BATCH, 256>>>(emb);

    // xh = emb2 @ wih2^T + b_ih + b_hh : bf16 3-term, M=8192, N=1024
    {
        int mblocks = (SEQ * BATCH) / BM;   // 64
        int nblocks = HID / BN;             // 8
        gemm_tc<false><<<mblocks * nblocks, 128, SMEM_TC>>>(
            (const char*)p_emb2, (const char*)p_wih2, p_xh, b_ih, b_hh,
            mblocks, HID, 2, K2, K2, K2 / BKK);
    }

    // recurrence: one persistent kernel, 128 resident blocks
    k_rnn_persist<<<RNN_BLOCKS, 256>>>(W_hh);

    // outputs = hallf @ wfcf^T + b_fc : fp16 1-term, M=8192, N=32000, K=1024
    {
        int mblocks = (SEQ * BATCH) / BM;   // 64
        int nblocks = OUT_DIM / BN;         // 250
        gemm_tc<true><<<mblocks * nblocks, 128, SMEM_TC>>>(
            (const char*)p_hallf, (const char*)p_wfcf, out, b_fc, nullptr,
            mblocks, OUT_DIM, 1, KF1, HID, KF1 / BKK);
    }

    k_store_hidden<<<(BATCH * HID + 255) / 256, 256>>>(out + (size_t)SEQ * BATCH * OUT_DIM);
}

// round 7
// speedup vs baseline: 2.5110x; 1.1518x over previous
#include <cuda_runtime.h>
#include <cuda_bf16.h>
#include <cuda_fp16.h>
#include <cstdint>
#include <cstddef>

#define SEQ 128
#define BATCH 64
#define EMB 1024
#define HID 1024
#define OUT_DIM 32000
#define VOCAB 32000
#define KCH 8
#define RNN_BLOCKS 128

// HMMA GEMM config (xh + output): 128x128 block, 4 warps of 64x64, BK=32, 4 stages
#define K2 3072                  // bf16 3-term
#define KF1 1024                 // fp16 1-term (output path)
#define BM 128
#define BN 128
#define BKK 32
#define SROW 80
#define STG_BYTES_TC ((BM + BN) * SROW)
#define STAGES_TC 4
#define SMEM_TC (STAGES_TC * STG_BYTES_TC)       // 81920

// recurrence persistent kernel config
#define CH3 384                  // bf16 elems per 128-fp32-k chunk (3 terms)
#define SUBC 12                  // k32 subchunks per block slice
#define SA_BYTES (SUBC * 64 * SROW)              // 61440
#define SMEM_RNN (2 * SA_BYTES)                  // 122880

// ---------------- device scratch ----------------
__device__ __align__(16) float g_xh[SEQ * BATCH * HID];
__device__ __align__(16) float g_h[BATCH * HID];
__device__ __align__(16) float g_part[KCH * BATCH * HID];
__device__ __align__(16) __half g_hallf[SEQ * BATCH * KF1];           // 16.8 MB
__device__ __align__(16) __half g_wfcf[OUT_DIM * HID];                // 64 MB
__device__ __align__(16) __nv_bfloat16 g_wih2[HID * K2];              // 6 MB
__device__ __align__(16) __nv_bfloat16 g_emb2[SEQ * BATCH * K2];      // 48 MB
__device__ __align__(16) __nv_bfloat16 g_whh2[HID * K2];              // 6 MB  [hi|lo|hi] chunked
__device__ __align__(16) __nv_bfloat16 g_h2[BATCH * K2];              // 384KB [hi|hi|lo] chunked
__device__ int g_idx[SEQ * BATCH];
__device__ int g_is64;
__device__ unsigned g_arrive;

// ---------------- helpers ----------------
__device__ __forceinline__ uint32_t smem_u32(const void* p) {
    uint32_t a;
    asm("{ .reg .u64 t; cvta.to.shared.u64 t, %1; cvt.u32.u64 %0, t; }" : "=r"(a) : "l"(p));
    return a;
}
__device__ __forceinline__ void cp16(uint32_t s, const void* g) {
    asm volatile("cp.async.cg.shared.global [%0], [%1], 16;" :: "r"(s), "l"(g) : "memory");
}
__device__ __forceinline__ void ldmx4(uint32_t& r0, uint32_t& r1, uint32_t& r2, uint32_t& r3, uint32_t addr) {
    asm volatile("ldmatrix.sync.aligned.m8n8.x4.shared.b16 {%0,%1,%2,%3}, [%4];"
                 : "=r"(r0), "=r"(r1), "=r"(r2), "=r"(r3) : "r"(addr));
}
__device__ __forceinline__ void mma_bf16(float* c, const uint32_t* a, const uint32_t* b) {
    asm volatile("mma.sync.aligned.m16n8k16.row.col.f32.bf16.bf16.f32 "
                 "{%0,%1,%2,%3}, {%4,%5,%6,%7}, {%8,%9}, {%0,%1,%2,%3};"
                 : "+f"(c[0]), "+f"(c[1]), "+f"(c[2]), "+f"(c[3])
                 : "r"(a[0]), "r"(a[1]), "r"(a[2]), "r"(a[3]), "r"(b[0]), "r"(b[1]));
}
__device__ __forceinline__ void mma_fp16(float* c, const uint32_t* a, const uint32_t* b) {
    asm volatile("mma.sync.aligned.m16n8k16.row.col.f32.f16.f16.f32 "
                 "{%0,%1,%2,%3}, {%4,%5,%6,%7}, {%8,%9}, {%0,%1,%2,%3};"
                 : "+f"(c[0]), "+f"(c[1]), "+f"(c[2]), "+f"(c[3])
                 : "r"(a[0]), "r"(a[1]), "r"(a[2]), "r"(a[3]), "r"(b[0]), "r"(b[1]));
}
// grid sync: release/acquire monotonic counter
__device__ __forceinline__ void gsync(unsigned target) {
    __syncthreads();
    if (threadIdx.x == 0) {
        asm volatile("red.release.gpu.global.add.u32 [%0], 1;" :: "l"(&g_arrive) : "memory");
        unsigned v;
        do {
            asm volatile("ld.acquire.gpu.global.u32 %0, [%1];" : "=r"(v) : "l"(&g_arrive) : "memory");
        } while (v < target);
    }
    __syncthreads();
}

// ---------------- small kernels ----------------
__global__ void k_sniff(const void* x) {
    __shared__ int bad;
    if (threadIdx.x == 0) bad = 0;
    __syncthreads();
    const unsigned long long* p = (const unsigned long long*)x;
    int mybad = 0;
    for (int i = threadIdx.x; i < 4096; i += 256)
        if (p[i] >= (unsigned long long)VOCAB) mybad = 1;
    if (mybad) atomicOr(&bad, 1);
    __syncthreads();
    if (threadIdx.x == 0) g_is64 = bad ? 0 : 1;
}
__global__ void k_decode(const void* x) {
    int i = blockIdx.x * 256 + threadIdx.x;
    if (i >= SEQ * BATCH) return;
    if (g_is64) g_idx[i] = (int)((const long long*)x)[i];
    else        g_idx[i] = ((const int*)x)[i];
}
// init h (fp32 + bf16 chunked split) and reset grid-sync counter
__global__ void k_copyh(const float* __restrict__ hidden) {
    int i = blockIdx.x * 256 + threadIdx.x;
    if (i == 0) g_arrive = 0;
    if (i >= BATCH * HID) return;
    float v = hidden[i];
    g_h[i] = v;
    __nv_bfloat16 hi = __float2bfloat16(v);
    __nv_bfloat16 lo = __float2bfloat16(v - __bfloat162float(hi));
    int b = i >> 10, j = i & 1023;
    int c = j >> 7, o = j & 127;
    __nv_bfloat16* hb = g_h2 + (size_t)b * K2 + c * CH3 + o;
    hb[0] = hi; hb[128] = hi; hb[256] = lo;
}
// W_ih fp32 -> bf16 segments [hi | lo | hi] (segment layout, xh path)
__global__ void k_convw_bf(const float* __restrict__ W) {
    int i = blockIdx.x * 256 + threadIdx.x;
    if (i >= HID * HID) return;
    float v = W[i];
    __nv_bfloat16 hi = __float2bfloat16(v);
    __nv_bfloat16 lo = __float2bfloat16(v - __bfloat162float(hi));
    int row = i >> 10, k = i & 1023;
    size_t base = (size_t)row * K2 + k;
    g_wih2[base] = hi;
    g_wih2[base + 1024] = lo;
    g_wih2[base + 2048] = hi;
}
// W_hh fp32 -> bf16 chunked [hi | lo | hi] per 128-k chunk (recurrence B side)
__global__ void k_conv_whh(const float* __restrict__ W) {
    int i = blockIdx.x * 256 + threadIdx.x;
    if (i >= HID * HID) return;
    float v = W[i];
    __nv_bfloat16 hi = __float2bfloat16(v);
    __nv_bfloat16 lo = __float2bfloat16(v - __bfloat162float(hi));
    int row = i >> 10, j = i & 1023;
    int c = j >> 7, o = j & 127;
    __nv_bfloat16* b = g_whh2 + (size_t)row * K2 + c * CH3 + o;
    b[0] = hi; b[128] = lo; b[256] = hi;
}
// W_fc fp32 -> fp16
__global__ void k_convw_f(const float* __restrict__ W) {
    int i = blockIdx.x * 256 + threadIdx.x;
    if (i < OUT_DIM * HID) g_wfcf[i] = __float2half(W[i]);
}
// gather emb rows, split to bf16 segments [hi | hi | lo]
__global__ void k_gather_split(const float* __restrict__ emb) {
    int r = blockIdx.x;
    int t = threadIdx.x;
    long long src = g_idx[r];
    float4 v = ((const float4*)(emb + (size_t)src * 1024))[t];
    __nv_bfloat16 h0 = __float2bfloat16(v.x), h1 = __float2bfloat16(v.y);
    __nv_bfloat16 h2 = __float2bfloat16(v.z), h3 = __float2bfloat16(v.w);
    __nv_bfloat16 l0 = __float2bfloat16(v.x - __bfloat162float(h0));
    __nv_bfloat16 l1 = __float2bfloat16(v.y - __bfloat162float(h1));
    __nv_bfloat16 l2 = __float2bfloat16(v.z - __bfloat162float(h2));
    __nv_bfloat16 l3 = __float2bfloat16(v.w - __bfloat162float(h3));
    uint2 hp, lp;
    ((__nv_bfloat16*)&hp)[0] = h0; ((__nv_bfloat16*)&hp)[1] = h1;
    ((__nv_bfloat16*)&hp)[2] = h2; ((__nv_bfloat16*)&hp)[3] = h3;
    ((__nv_bfloat16*)&lp)[0] = l0; ((__nv_bfloat16*)&lp)[1] = l1;
    ((__nv_bfloat16*)&lp)[2] = l2; ((__nv_bfloat16*)&lp)[3] = l3;
    __nv_bfloat16* base = g_emb2 + (size_t)r * K2;
    ((uint2*)base)[t] = hp;
    ((uint2*)(base + 1024))[t] = hp;
    ((uint2*)(base + 2048))[t] = lp;
}

// ---------------- persistent recurrence (HMMA bf16 3-term) ----------------
// 128 blocks x 256 thr (8 warps 2x4), 1/SM. Block (nx,kz): 64x64 partial tile,
// K-chunk = 384 bf16 (=128 fp32 k). W slice resident in SMEM all steps.
__global__ void __launch_bounds__(256) k_rnn_persist(float* __restrict__ out) {
    extern __shared__ __align__(16) char smem[];
    const uint32_t sA = smem_u32(smem);
    const uint32_t sB = sA + SA_BYTES;
    const int t = threadIdx.x;
    const int lane = t & 31, wid = t >> 5;
    const int warp_m = wid & 1;          // 2 x 32 rows
    const int warp_n = wid >> 1;         // 4 x 16 cols
    const int bid = blockIdx.x;
    const int nx = bid & 15, kz = bid >> 4;
    const int n0 = nx * 64;
    const int r = t >> 2, q = t & 3;

    const char* hsrc = (const char*)g_h2 + ((size_t)r * K2 + kz * CH3 + q * 8) * 2;
    const char* wsrc = (const char*)g_whh2 + ((size_t)(n0 + r) * K2 + kz * CH3 + q * 8) * 2;
    const uint32_t sAoff = sA + r * SROW + q * 16;
    const uint32_t sBoff = sB + r * SROW + q * 16;

    const int arow = ((lane >> 3) & 1) * 8 + (lane & 7);
    const int ahalf = (lane >> 4) & 1;
    const int brow = ((lane >> 4) & 1) * 8 + (lane & 7);
    const int bhalf = (lane >> 3) & 1;

    float* partBase = g_part + (size_t)kz * (BATCH * HID);
    const int i0 = bid * 512 + t;

    // W slice -> SMEM once
#pragma unroll
    for (int i = 0; i < SUBC; i++) cp16(sBoff + i * (64 * SROW), wsrc + i * 64);
    asm volatile("cp.async.commit_group;" ::: "memory");
    asm volatile("cp.async.wait_group 0;" ::: "memory");
    __syncthreads();

    unsigned target = 0;
    for (int s = 0; s < SEQ; s++) {
        // phase A: load h slice, mma 64x64 partial
#pragma unroll
        for (int i = 0; i < SUBC; i++) cp16(sAoff + i * (64 * SROW), hsrc + i * 64);
        asm volatile("cp.async.commit_group;" ::: "memory");
        asm volatile("cp.async.wait_group 0;" ::: "memory");
        __syncthreads();

        float acc[2][2][4];
#pragma unroll
        for (int mt = 0; mt < 2; mt++)
#pragma unroll
            for (int nt = 0; nt < 2; nt++)
#pragma unroll
                for (int e = 0; e < 4; e++) acc[mt][nt][e] = 0.f;

#pragma unroll
        for (int sc = 0; sc < SUBC; sc++) {
#pragma unroll
            for (int kp = 0; kp < 2; kp++) {
                uint32_t af[2][4], bf[4];
#pragma unroll
                for (int mt = 0; mt < 2; mt++)
                    ldmx4(af[mt][0], af[mt][1], af[mt][2], af[mt][3],
                          sA + sc * (64 * SROW) + (warp_m * 32 + mt * 16 + arow) * SROW + ahalf * 16 + kp * 32);
                ldmx4(bf[0], bf[1], bf[2], bf[3],
                      sB + sc * (64 * SROW) + (warp_n * 16 + brow) * SROW + bhalf * 16 + kp * 32);
                mma_bf16(acc[0][0], af[0], &bf[0]);
                mma_bf16(acc[0][1], af[0], &bf[2]);
                mma_bf16(acc[1][0], af[1], &bf[0]);
                mma_bf16(acc[1][1], af[1], &bf[2]);
            }
        }
#pragma unroll
        for (int mt = 0; mt < 2; mt++) {
            int row = warp_m * 32 + mt * 16 + (lane >> 2);
#pragma unroll
            for (int nt = 0; nt < 2; nt++) {
                int col = n0 + warp_n * 16 + nt * 8 + (lane & 3) * 2;
                __stcg((float2*)&partBase[(size_t)row * 1024 + col],
                       make_float2(acc[mt][nt][0], acc[mt][nt][1]));
                __stcg((float2*)&partBase[(size_t)(row + 8) * 1024 + col],
                       make_float2(acc[mt][nt][2], acc[mt][nt][3]));
            }
        }

        target += RNN_BLOCKS;
        gsync(target);

        // phase B: reduce + tanh + emits
        const float* xh_s = g_xh + (size_t)s * (BATCH * HID);
#pragma unroll
        for (int e = 0; e < 2; e++) {
            int i = i0 + e * 256;
            float v = xh_s[i];
#pragma unroll
            for (int kc = 0; kc < KCH; kc++)
                v += __ldcg(&g_part[(size_t)kc * (BATCH * HID) + i]);
            float h = tanhf(v);
            __stcg(&g_h[i], h);
            int b = i >> 10, j = i & 1023;
            g_hallf[(size_t)(s * BATCH + b) * KF1 + j] = __float2half(h);
            __nv_bfloat16 hi = __float2bfloat16(h);
            __nv_bfloat16 lo = __float2bfloat16(h - __bfloat162float(hi));
            int c = j >> 7, o = j & 127;
            __nv_bfloat16* hb = g_h2 + (size_t)b * K2 + c * CH3 + o;
            hb[0] = hi; hb[128] = hi; hb[256] = lo;
        }

        target += RNN_BLOCKS;
        gsync(target);
    }

    // final hidden -> out tail
#pragma unroll
    for (int e = 0; e < 2; e++) {
        int i = i0 + e * 256;
        out[(size_t)SEQ * BATCH * OUT_DIM + i] = __ldcg(&g_h[i]);
    }
}

// ---------------- HMMA GEMM: C[M,N] = A @ B^T + bias ----------------
template<bool FP16>
__global__ void __launch_bounds__(128, 2)
gemm_tc(const char* __restrict__ A2, const char* __restrict__ B2,
        float* __restrict__ C, const float* __restrict__ bias0,
        const float* __restrict__ bias1, int mblocks, int ldc, int nbias,
        int kaElems, int kbElems, int nkt)
{
    extern __shared__ __align__(16) char smem[];
    const uint32_t sBase = smem_u32(smem);
    const int t = threadIdx.x;
    const int lane = t & 31, wid = t >> 5;
    const int warp_m = wid & 1;
    const int warp_n = wid >> 1;

    const int m0 = (blockIdx.x % mblocks) * BM;
    const int n0 = (blockIdx.x / mblocks) * BN;

    uint32_t soffA[4], soffB[4];
    const char *gA[4], *gB[4];
#pragma unroll
    for (int i = 0; i < 4; i++) {
        int c = t + 128 * i;
        int row = c >> 2, q = c & 3;
        soffA[i] = (uint32_t)(row * SROW + q * 16);
        soffB[i] = (uint32_t)(BM * SROW + row * SROW + q * 16);
        gA[i] = A2 + ((size_t)(m0 + row) * kaElems + q * 8) * 2;
        gB[i] = B2 + ((size_t)(n0 + row) * kbElems + q * 8) * 2;
    }

    const int arow = ((lane >> 3) & 1) * 8 + (lane & 7);
    const int ahalf = (lane >> 4) & 1;
    const uint32_t aOff = (uint32_t)((warp_m * 64 + arow) * SROW + ahalf * 16);
    const int brow = ((lane >> 4) & 1) * 8 + (lane & 7);
    const int bhalf = (lane >> 3) & 1;
    const uint32_t bOff = (uint32_t)(BM * SROW + (warp_n * 64 + brow) * SROW + bhalf * 16);

    float acc[4][8][4];
#pragma unroll
    for (int mt = 0; mt < 4; mt++)
#pragma unroll
        for (int nt = 0; nt < 8; nt++)
#pragma unroll
            for (int e = 0; e < 4; e++) acc[mt][nt][e] = 0.f;

#pragma unroll
    for (int p = 0; p < STAGES_TC - 1; p++) {
        uint32_t stg = sBase + p * STG_BYTES_TC;
        size_t ko = (size_t)p * 64;
#pragma unroll
        for (int i = 0; i < 4; i++) cp16(stg + soffA[i], gA[i] + ko);
#pragma unroll
        for (int i = 0; i < 4; i++) cp16(stg + soffB[i], gB[i] + ko);
        asm volatile("cp.async.commit_group;" ::: "memory");
    }

    for (int kt = 0; kt < nkt; kt++) {
        if (kt < nkt - 2)       asm volatile("cp.async.wait_group 2;" ::: "memory");
        else if (kt == nkt - 2) asm volatile("cp.async.wait_group 1;" ::: "memory");
        else                    asm volatile("cp.async.wait_group 0;" ::: "memory");
        __syncthreads();

        if (kt + 3 < nkt) {
            uint32_t stg2 = sBase + ((kt + 3) & 3) * STG_BYTES_TC;
            size_t ko = (size_t)(kt + 3) * 64;
#pragma unroll
            for (int i = 0; i < 4; i++) cp16(stg2 + soffA[i], gA[i] + ko);
#pragma unroll
            for (int i = 0; i < 4; i++) cp16(stg2 + soffB[i], gB[i] + ko);
            asm volatile("cp.async.commit_group;" ::: "memory");
        }

        const uint32_t stg = sBase + (kt & 3) * STG_BYTES_TC;
#pragma unroll
        for (int kp = 0; kp < 2; kp++) {
            uint32_t af[4][4], bf[4][4];
#pragma unroll
            for (int mt = 0; mt < 4; mt++)
                ldmx4(af[mt][0], af[mt][1], af[mt][2], af[mt][3],
                      stg + aOff + mt * 16 * SROW + kp * 32);
#pragma unroll
            for (int p = 0; p < 4; p++)
                ldmx4(bf[p][0], bf[p][1], bf[p][2], bf[p][3],
                      stg + bOff + p * 16 * SROW + kp * 32);
#pragma unroll
            for (int mt = 0; mt < 4; mt++)
#pragma unroll
                for (int nt = 0; nt < 8; nt++) {
                    if (FP16) mma_fp16(acc[mt][nt], af[mt], &bf[nt >> 1][(nt & 1) * 2]);
                    else      mma_bf16(acc[mt][nt], af[mt], &bf[nt >> 1][(nt & 1) * 2]);
                }
        }
    }

#pragma unroll
    for (int mt = 0; mt < 4; mt++) {
        int row = m0 + warp_m * 64 + mt * 16 + (lane >> 2);
#pragma unroll
        for (int nt = 0; nt < 8; nt++) {
            int col = n0 + warp_n * 64 + nt * 8 + (lane & 3) * 2;
            float b0 = 0.f, b1 = 0.f;
            if (nbias >= 1) { b0 += __ldg(&bias0[col]); b1 += __ldg(&bias0[col + 1]); }
            if (nbias >= 2) { b0 += __ldg(&bias1[col]); b1 += __ldg(&bias1[col + 1]); }
            float2 v0 = make_float2(acc[mt][nt][0] + b0, acc[mt][nt][1] + b1);
            float2 v1 = make_float2(acc[mt][nt][2] + b0, acc[mt][nt][3] + b1);
            *(float2*)&C[(size_t)row * ldc + col] = v0;
            *(float2*)&C[(size_t)(row + 8) * ldc + col] = v1;
        }
    }
}

// ---------------- launch ----------------
extern "C" void kernel_launch(void* const* d_in, const int* in_sizes, int n_in,
                              void* d_out, int out_size)
{
    const void*  x      = d_in[0];
    const float* hidden = (const float*)d_in[1];
    const float* emb    = (const float*)d_in[2];
    const float* W_ih   = (const float*)d_in[3];
    const float* W_hh   = (const float*)d_in[4];
    const float* b_ih   = (const float*)d_in[5];
    const float* b_hh   = (const float*)d_in[6];
    const float* W_fc   = (const float*)d_in[7];
    const float* b_fc   = (const float*)d_in[8];
    float* out = (float*)d_out;

    float* p_xh;
    void *p_hallf, *p_wfcf, *p_wih2, *p_emb2;
    cudaGetSymbolAddress((void**)&p_xh, g_xh);
    cudaGetSymbolAddress(&p_hallf, g_hallf);
    cudaGetSymbolAddress(&p_wfcf,  g_wfcf);
    cudaGetSymbolAddress(&p_wih2,  g_wih2);
    cudaGetSymbolAddress(&p_emb2,  g_emb2);

    cudaFuncSetAttribute(gemm_tc<true>,  cudaFuncAttributeMaxDynamicSharedMemorySize, SMEM_TC);
    cudaFuncSetAttribute(gemm_tc<false>, cudaFuncAttributeMaxDynamicSharedMemorySize, SMEM_TC);
    cudaFuncSetAttribute(k_rnn_persist,  cudaFuncAttributeMaxDynamicSharedMemorySize, SMEM_RNN);

    k_sniff<<<1, 256>>>(x);
    k_decode<<<(SEQ * BATCH + 255) / 256, 256>>>(x);
    k_copyh<<<(BATCH * HID + 255) / 256, 256>>>(hidden);
    k_convw_bf<<<(HID * HID) / 256, 256>>>(W_ih);
    k_conv_whh<<<(HID * HID) / 256, 256>>>(W_hh);
    k_convw_f<<<(OUT_DIM * HID) / 256, 256>>>(W_fc);
    k_gather_split<<<SEQ * BATCH, 256>>>(emb);

    // xh = emb2 @ wih2^T + b_ih + b_hh : bf16 3-term, M=8192, N=1024
    {
        int mblocks = (SEQ * BATCH) / BM;   // 64
        int nblocks = HID / BN;             // 8
        gemm_tc<false><<<mblocks * nblocks, 128, SMEM_TC>>>(
            (const char*)p_emb2, (const char*)p_wih2, p_xh, b_ih, b_hh,
            mblocks, HID, 2, K2, K2, K2 / BKK);
    }

    // recurrence: persistent HMMA kernel (also writes final hidden to out tail)
    k_rnn_persist<<<RNN_BLOCKS, 256, SMEM_RNN>>>(out);

    // outputs = hallf @ wfcf^T + b_fc : fp16 1-term, M=8192, N=32000, K=1024
    {
        int mblocks = (SEQ * BATCH) / BM;   // 64
        int nblocks = OUT_DIM / BN;         // 250
        gemm_tc<true><<<mblocks * nblocks, 128, SMEM_TC>>>(
            (const char*)p_hallf, (const char*)p_wfcf, out, b_fc, nullptr,
            mblocks, OUT_DIM, 1, KF1, HID, KF1 / BKK);
    }
}

// round 8
// speedup vs baseline: 2.6117x; 1.0401x over previous
#include <cuda_runtime.h>
#include <cuda_bf16.h>
#include <cuda_fp16.h>
#include <cstdint>
#include <cstddef>

#define SEQ 128
#define BATCH 64
#define EMB 1024
#define HID 1024
#define OUT_DIM 32000
#define VOCAB 32000
#define RNN_BLOCKS 128

// HMMA GEMM config: 128x128 block, 4 warps of 64x64, BK=32, 4 stages
#define KE 2048                  // fp16 2-term (xh path, A side)
#define KF1 1024                 // fp16 1-term (output path)
#define BM 128
#define BN 128
#define BKK 32
#define SROW 80
#define STG_BYTES_TC ((BM + BN) * SROW)
#define STAGES_TC 4
#define SMEM_TC (STAGES_TC * STG_BYTES_TC)       // 81920

// recurrence persistent kernel config
#define K2 3072                  // bf16 3-term chunked (recurrence)
#define CH3 384
#define SUBC 12
#define SA_BYTES (SUBC * 64 * SROW)              // 61440
#define SMEM_RNN (2 * SA_BYTES)                  // 122880

// ---------------- device scratch ----------------
__device__ __align__(16) float g_xh[SEQ * BATCH * HID];               // xh + biases; phase-A reds land here
__device__ __align__(16) float g_h[BATCH * HID];
__device__ __align__(16) __half g_hallf[SEQ * BATCH * KF1];           // 16.8 MB
__device__ __align__(16) __half g_wfcf[OUT_DIM * HID];                // 64 MB
__device__ __align__(16) __half g_wihf[HID * HID];                    // 2 MB
__device__ __align__(16) __half g_embf[SEQ * BATCH * KE];             // 33.5 MB [hi|lo]
__device__ __align__(16) __nv_bfloat16 g_whh2[HID * K2];              // 6 MB [hi|lo|hi] chunked
__device__ __align__(16) __nv_bfloat16 g_h2[BATCH * K2];              // 384KB [hi|hi|lo] chunked
__device__ int g_idx[SEQ * BATCH];
__device__ int g_is64;
__device__ unsigned g_arrive;

// ---------------- helpers ----------------
__device__ __forceinline__ uint32_t smem_u32(const void* p) {
    uint32_t a;
    asm("{ .reg .u64 t; cvta.to.shared.u64 t, %1; cvt.u32.u64 %0, t; }" : "=r"(a) : "l"(p));
    return a;
}
__device__ __forceinline__ void cp16(uint32_t s, const void* g) {
    asm volatile("cp.async.cg.shared.global [%0], [%1], 16;" :: "r"(s), "l"(g) : "memory");
}
__device__ __forceinline__ void ldmx4(uint32_t& r0, uint32_t& r1, uint32_t& r2, uint32_t& r3, uint32_t addr) {
    asm volatile("ldmatrix.sync.aligned.m8n8.x4.shared.b16 {%0,%1,%2,%3}, [%4];"
                 : "=r"(r0), "=r"(r1), "=r"(r2), "=r"(r3) : "r"(addr));
}
__device__ __forceinline__ void mma_bf16(float* c, const uint32_t* a, const uint32_t* b) {
    asm volatile("mma.sync.aligned.m16n8k16.row.col.f32.bf16.bf16.f32 "
                 "{%0,%1,%2,%3}, {%4,%5,%6,%7}, {%8,%9}, {%0,%1,%2,%3};"
                 : "+f"(c[0]), "+f"(c[1]), "+f"(c[2]), "+f"(c[3])
                 : "r"(a[0]), "r"(a[1]), "r"(a[2]), "r"(a[3]), "r"(b[0]), "r"(b[1]));
}
__device__ __forceinline__ void mma_fp16(float* c, const uint32_t* a, const uint32_t* b) {
    asm volatile("mma.sync.aligned.m16n8k16.row.col.f32.f16.f16.f32 "
                 "{%0,%1,%2,%3}, {%4,%5,%6,%7}, {%8,%9}, {%0,%1,%2,%3};"
                 : "+f"(c[0]), "+f"(c[1]), "+f"(c[2]), "+f"(c[3])
                 : "r"(a[0]), "r"(a[1]), "r"(a[2]), "r"(a[3]), "r"(b[0]), "r"(b[1]));
}
__device__ __forceinline__ void redadd(float* p, float v) {
    asm volatile("red.relaxed.gpu.global.add.f32 [%0], %1;" :: "l"(p), "f"(v) : "memory");
}
// grid sync: release/acquire monotonic counter
__device__ __forceinline__ void gsync(unsigned target) {
    __syncthreads();
    if (threadIdx.x == 0) {
        asm volatile("red.release.gpu.global.add.u32 [%0], 1;" :: "l"(&g_arrive) : "memory");
        unsigned v;
        do {
            asm volatile("ld.acquire.gpu.global.u32 %0, [%1];" : "=r"(v) : "l"(&g_arrive) : "memory");
        } while (v < target);
    }
    __syncthreads();
}

// ---------------- small kernels ----------------
__global__ void k_sniff(const void* x) {
    __shared__ int bad;
    if (threadIdx.x == 0) bad = 0;
    __syncthreads();
    const unsigned long long* p = (const unsigned long long*)x;
    int mybad = 0;
    for (int i = threadIdx.x; i < 4096; i += 256)
        if (p[i] >= (unsigned long long)VOCAB) mybad = 1;
    if (mybad) atomicOr(&bad, 1);
    __syncthreads();
    if (threadIdx.x == 0) g_is64 = bad ? 0 : 1;
}
__global__ void k_decode(const void* x) {
    int i = blockIdx.x * 256 + threadIdx.x;
    if (i >= SEQ * BATCH) return;
    if (g_is64) g_idx[i] = (int)((const long long*)x)[i];
    else        g_idx[i] = ((const int*)x)[i];
}
// init h2 (bf16 chunked split) and reset grid-sync counter
__global__ void k_copyh(const float* __restrict__ hidden) {
    int i = blockIdx.x * 256 + threadIdx.x;
    if (i == 0) g_arrive = 0;
    if (i >= BATCH * HID) return;
    float v = hidden[i];
    g_h[i] = v;
    __nv_bfloat16 hi = __float2bfloat16(v);
    __nv_bfloat16 lo = __float2bfloat16(v - __bfloat162float(hi));
    int b = i >> 10, j = i & 1023;
    int c = j >> 7, o = j & 127;
    __nv_bfloat16* hb = g_h2 + (size_t)b * K2 + c * CH3 + o;
    hb[0] = hi; hb[128] = hi; hb[256] = lo;
}
// W_hh fp32 -> bf16 chunked [hi | lo | hi] per 128-k chunk
__global__ void k_conv_whh(const float* __restrict__ W) {
    int i = blockIdx.x * 256 + threadIdx.x;
    if (i >= HID * HID) return;
    float v = W[i];
    __nv_bfloat16 hi = __float2bfloat16(v);
    __nv_bfloat16 lo = __float2bfloat16(v - __bfloat162float(hi));
    int row = i >> 10, j = i & 1023;
    int c = j >> 7, o = j & 127;
    __nv_bfloat16* b = g_whh2 + (size_t)row * K2 + c * CH3 + o;
    b[0] = hi; b[128] = lo; b[256] = hi;
}
// fp32 -> fp16 (vectorized), for W_fc and W_ih
__global__ void k_convw_f(const float* __restrict__ W, __half* __restrict__ dst, int n4) {
    int i = blockIdx.x * 256 + threadIdx.x;
    if (i >= n4) return;
    float4 v = ((const float4*)W)[i];
    __half2 a = __floats2half2_rn(v.x, v.y);
    __half2 b = __floats2half2_rn(v.z, v.w);
    ((uint2*)dst)[i] = make_uint2(*(uint32_t*)&a, *(uint32_t*)&b);
}
// gather emb rows, split to fp16 segments [hi | lo]
__global__ void k_gather_split(const float* __restrict__ emb) {
    int r = blockIdx.x;
    int t = threadIdx.x;
    long long src = g_idx[r];
    float4 v = ((const float4*)(emb + (size_t)src * 1024))[t];
    __half h0 = __float2half(v.x), h1 = __float2half(v.y);
    __half h2 = __float2half(v.z), h3 = __float2half(v.w);
    __half l0 = __float2half(v.x - __half2float(h0));
    __half l1 = __float2half(v.y - __half2float(h1));
    __half l2 = __float2half(v.z - __half2float(h2));
    __half l3 = __float2half(v.w - __half2float(h3));
    uint2 hp, lp;
    ((__half*)&hp)[0] = h0; ((__half*)&hp)[1] = h1;
    ((__half*)&hp)[2] = h2; ((__half*)&hp)[3] = h3;
    ((__half*)&lp)[0] = l0; ((__half*)&lp)[1] = l1;
    ((__half*)&lp)[2] = l2; ((__half*)&lp)[3] = l3;
    __half* base = g_embf + (size_t)r * KE;
    ((uint2*)base)[t] = hp;
    ((uint2*)(base + 1024))[t] = lp;
}

// ---------------- persistent recurrence (HMMA bf16 3-term) ----------------
// 128 blocks (16 nx x 8 kz) x 256 thr. W slice SMEM-resident all steps.
// Phase A: 64x64 partial -> red.add directly into g_xh[s] (pre-initialized
// with xh+biases). Phase B: single load + tanh + emits.
__global__ void __launch_bounds__(256) k_rnn_persist(float* __restrict__ out) {
    extern __shared__ __align__(16) char smem[];
    const uint32_t sA = smem_u32(smem);
    const uint32_t sB = sA + SA_BYTES;
    const int t = threadIdx.x;
    const int lane = t & 31, wid = t >> 5;
    const int warp_m = wid & 1;
    const int warp_n = wid >> 1;
    const int bid = blockIdx.x;
    const int nx = bid & 15, kz = bid >> 4;
    const int n0 = nx * 64;
    const int r = t >> 2, q = t & 3;

    const char* hsrc = (const char*)g_h2 + ((size_t)r * K2 + kz * CH3 + q * 8) * 2;
    const char* wsrc = (const char*)g_whh2 + ((size_t)(n0 + r) * K2 + kz * CH3 + q * 8) * 2;
    const uint32_t sAoff = sA + r * SROW + q * 16;
    const uint32_t sBoff = sB + r * SROW + q * 16;

    const int arow = ((lane >> 3) & 1) * 8 + (lane & 7);
    const int ahalf = (lane >> 4) & 1;
    const int brow = ((lane >> 4) & 1) * 8 + (lane & 7);
    const int bhalf = (lane >> 3) & 1;

    const int i0 = bid * 512 + t;

    // W slice -> SMEM once
#pragma unroll
    for (int i = 0; i < SUBC; i++) cp16(sBoff + i * (64 * SROW), wsrc + i * 64);
    asm volatile("cp.async.commit_group;" ::: "memory");
    asm volatile("cp.async.wait_group 0;" ::: "memory");
    __syncthreads();

    unsigned target = 0;
    for (int s = 0; s < SEQ; s++) {
        float* xs = g_xh + (size_t)s * (BATCH * HID);

        // phase A: load h slice, mma 64x64 partial, red into xs
#pragma unroll
        for (int i = 0; i < SUBC; i++) cp16(sAoff + i * (64 * SROW), hsrc + i * 64);
        asm volatile("cp.async.commit_group;" ::: "memory");
        asm volatile("cp.async.wait_group 0;" ::: "memory");
        __syncthreads();

        float acc[2][2][4];
#pragma unroll
        for (int mt = 0; mt < 2; mt++)
#pragma unroll
            for (int nt = 0; nt < 2; nt++)
#pragma unroll
                for (int e = 0; e < 4; e++) acc[mt][nt][e] = 0.f;

#pragma unroll
        for (int sc = 0; sc < SUBC; sc++) {
#pragma unroll
            for (int kp = 0; kp < 2; kp++) {
                uint32_t af[2][4], bf[4];
#pragma unroll
                for (int mt = 0; mt < 2; mt++)
                    ldmx4(af[mt][0], af[mt][1], af[mt][2], af[mt][3],
                          sA + sc * (64 * SROW) + (warp_m * 32 + mt * 16 + arow) * SROW + ahalf * 16 + kp * 32);
                ldmx4(bf[0], bf[1], bf[2], bf[3],
                      sB + sc * (64 * SROW) + (warp_n * 16 + brow) * SROW + bhalf * 16 + kp * 32);
                mma_bf16(acc[0][0], af[0], &bf[0]);
                mma_bf16(acc[0][1], af[0], &bf[2]);
                mma_bf16(acc[1][0], af[1], &bf[0]);
                mma_bf16(acc[1][1], af[1], &bf[2]);
            }
        }
#pragma unroll
        for (int mt = 0; mt < 2; mt++) {
            int row = warp_m * 32 + mt * 16 + (lane >> 2);
#pragma unroll
            for (int nt = 0; nt < 2; nt++) {
                int col = n0 + warp_n * 16 + nt * 8 + (lane & 3) * 2;
                redadd(&xs[(size_t)row * 1024 + col],     acc[mt][nt][0]);
                redadd(&xs[(size_t)row * 1024 + col + 1], acc[mt][nt][1]);
                redadd(&xs[(size_t)(row + 8) * 1024 + col],     acc[mt][nt][2]);
                redadd(&xs[(size_t)(row + 8) * 1024 + col + 1], acc[mt][nt][3]);
            }
        }

        target += RNN_BLOCKS;
        gsync(target);

        // phase B: tanh + emits
#pragma unroll
        for (int e = 0; e < 2; e++) {
            int i = i0 + e * 256;
            float h = tanhf(__ldcg(&xs[i]));
            int b = i >> 10, j = i & 1023;
            g_hallf[(size_t)(s * BATCH + b) * KF1 + j] = __float2half(h);
            __nv_bfloat16 hi = __float2bfloat16(h);
            __nv_bfloat16 lo = __float2bfloat16(h - __bfloat162float(hi));
            int c = j >> 7, o = j & 127;
            __nv_bfloat16* hb = g_h2 + (size_t)b * K2 + c * CH3 + o;
            hb[0] = hi; hb[128] = hi; hb[256] = lo;
            if (s == SEQ - 1) __stcg(&g_h[i], h);
        }

        target += RNN_BLOCKS;
        gsync(target);
    }

    // final hidden -> out tail
#pragma unroll
    for (int e = 0; e < 2; e++) {
        int i = i0 + e * 256;
        out[(size_t)SEQ * BATCH * OUT_DIM + i] = __ldcg(&g_h[i]);
    }
}

// ---------------- HMMA GEMM: C[M,N] = A @ B^T + bias ----------------
// 128x128 block, 4 warps (2x2) of 64x64. m-fastest. B k-chunk wraps by bkmask.
template<bool FP16>
__global__ void __launch_bounds__(128, 2)
gemm_tc(const char* __restrict__ A2, const char* __restrict__ B2,
        float* __restrict__ C, const float* __restrict__ bias0,
        const float* __restrict__ bias1, int mblocks, int ldc, int nbias,
        int kaElems, int kbElems, int nkt, int bkmask)
{
    extern __shared__ __align__(16) char smem[];
    const uint32_t sBase = smem_u32(smem);
    const int t = threadIdx.x;
    const int lane = t & 31, wid = t >> 5;
    const int warp_m = wid & 1;
    const int warp_n = wid >> 1;

    const int m0 = (blockIdx.x % mblocks) * BM;
    const int n0 = (blockIdx.x / mblocks) * BN;

    uint32_t soffA[4], soffB[4];
    const char *gA[4], *gB[4];
#pragma unroll
    for (int i = 0; i < 4; i++) {
        int c = t + 128 * i;
        int row = c >> 2, q = c & 3;
        soffA[i] = (uint32_t)(row * SROW + q * 16);
        soffB[i] = (uint32_t)(BM * SROW + row * SROW + q * 16);
        gA[i] = A2 + ((size_t)(m0 + row) * kaElems + q * 8) * 2;
        gB[i] = B2 + ((size_t)(n0 + row) * kbElems + q * 8) * 2;
    }

    const int arow = ((lane >> 3) & 1) * 8 + (lane & 7);
    const int ahalf = (lane >> 4) & 1;
    const uint32_t aOff = (uint32_t)((warp_m * 64 + arow) * SROW + ahalf * 16);
    const int brow = ((lane >> 4) & 1) * 8 + (lane & 7);
    const int bhalf = (lane >> 3) & 1;
    const uint32_t bOff = (uint32_t)(BM * SROW + (warp_n * 64 + brow) * SROW + bhalf * 16);

    float acc[4][8][4];
#pragma unroll
    for (int mt = 0; mt < 4; mt++)
#pragma unroll
        for (int nt = 0; nt < 8; nt++)
#pragma unroll
            for (int e = 0; e < 4; e++) acc[mt][nt][e] = 0.f;

#pragma unroll
    for (int p = 0; p < STAGES_TC - 1; p++) {
        uint32_t stg = sBase + p * STG_BYTES_TC;
        size_t ka = (size_t)p * 64;
        size_t kb = (size_t)(p & bkmask) * 64;
#pragma unroll
        for (int i = 0; i < 4; i++) cp16(stg + soffA[i], gA[i] + ka);
#pragma unroll
        for (int i = 0; i < 4; i++) cp16(stg + soffB[i], gB[i] + kb);
        asm volatile("cp.async.commit_group;" ::: "memory");
    }

    for (int kt = 0; kt < nkt; kt++) {
        if (kt < nkt - 2)       asm volatile("cp.async.wait_group 2;" ::: "memory");
        else if (kt == nkt - 2) asm volatile("cp.async.wait_group 1;" ::: "memory");
        else                    asm volatile("cp.async.wait_group 0;" ::: "memory");
        __syncthreads();

        if (kt + 3 < nkt) {
            uint32_t stg2 = sBase + ((kt + 3) & 3) * STG_BYTES_TC;
            size_t ka = (size_t)(kt + 3) * 64;
            size_t kb = (size_t)((kt + 3) & bkmask) * 64;
#pragma unroll
            for (int i = 0; i < 4; i++) cp16(stg2 + soffA[i], gA[i] + ka);
#pragma unroll
            for (int i = 0; i < 4; i++) cp16(stg2 + soffB[i], gB[i] + kb);
            asm volatile("cp.async.commit_group;" ::: "memory");
        }

        const uint32_t stg = sBase + (kt & 3) * STG_BYTES_TC;
#pragma unroll
        for (int kp = 0; kp < 2; kp++) {
            uint32_t af[4][4], bf[4][4];
#pragma unroll
            for (int mt = 0; mt < 4; mt++)
                ldmx4(af[mt][0], af[mt][1], af[mt][2], af[mt][3],
                      stg + aOff + mt * 16 * SROW + kp * 32);
#pragma unroll
            for (int p = 0; p < 4; p++)
                ldmx4(bf[p][0], bf[p][1], bf[p][2], bf[p][3],
                      stg + bOff + p * 16 * SROW + kp * 32);
#pragma unroll
            for (int mt = 0; mt < 4; mt++)
#pragma unroll
                for (int nt = 0; nt < 8; nt++) {
                    if (FP16) mma_fp16(acc[mt][nt], af[mt], &bf[nt >> 1][(nt & 1) * 2]);
                    else      mma_bf16(acc[mt][nt], af[mt], &bf[nt >> 1][(nt & 1) * 2]);
                }
        }
    }

#pragma unroll
    for (int mt = 0; mt < 4; mt++) {
        int row = m0 + warp_m * 64 + mt * 16 + (lane >> 2);
#pragma unroll
        for (int nt = 0; nt < 8; nt++) {
            int col = n0 + warp_n * 64 + nt * 8 + (lane & 3) * 2;
            float b0 = 0.f, b1 = 0.f;
            if (nbias >= 1) { b0 += __ldg(&bias0[col]); b1 += __ldg(&bias0[col + 1]); }
            if (nbias >= 2) { b0 += __ldg(&bias1[col]); b1 += __ldg(&bias1[col + 1]); }
            float2 v0 = make_float2(acc[mt][nt][0] + b0, acc[mt][nt][1] + b1);
            float2 v1 = make_float2(acc[mt][nt][2] + b0, acc[mt][nt][3] + b1);
            *(float2*)&C[(size_t)row * ldc + col] = v0;
            *(float2*)&C[(size_t)(row + 8) * ldc + col] = v1;
        }
    }
}

// ---------------- launch ----------------
extern "C" void kernel_launch(void* const* d_in, const int* in_sizes, int n_in,
                              void* d_out, int out_size)
{
    const void*  x      = d_in[0];
    const float* hidden = (const float*)d_in[1];
    const float* emb    = (const float*)d_in[2];
    const float* W_ih   = (const float*)d_in[3];
    const float* W_hh   = (const float*)d_in[4];
    const float* b_ih   = (const float*)d_in[5];
    const float* b_hh   = (const float*)d_in[6];
    const float* W_fc   = (const float*)d_in[7];
    const float* b_fc   = (const float*)d_in[8];
    float* out = (float*)d_out;

    float* p_xh;
    void *p_hallf, *p_wfcf, *p_wihf, *p_embf;
    cudaGetSymbolAddress((void**)&p_xh, g_xh);
    cudaGetSymbolAddress(&p_hallf, g_hallf);
    cudaGetSymbolAddress(&p_wfcf,  g_wfcf);
    cudaGetSymbolAddress(&p_wihf,  g_wihf);
    cudaGetSymbolAddress(&p_embf,  g_embf);

    cudaFuncSetAttribute(gemm_tc<true>,  cudaFuncAttributeMaxDynamicSharedMemorySize, SMEM_TC);
    cudaFuncSetAttribute(gemm_tc<false>, cudaFuncAttributeMaxDynamicSharedMemorySize, SMEM_TC);
    cudaFuncSetAttribute(k_rnn_persist,  cudaFuncAttributeMaxDynamicSharedMemorySize, SMEM_RNN);

    k_sniff<<<1, 256>>>(x);
    k_decode<<<(SEQ * BATCH + 255) / 256, 256>>>(x);
    k_copyh<<<(BATCH * HID + 255) / 256, 256>>>(hidden);
    k_conv_whh<<<(HID * HID) / 256, 256>>>(W_hh);
    k_convw_f<<<(HID * HID / 4 + 255) / 256, 256>>>(W_ih, (__half*)p_wihf, HID * HID / 4);
    k_convw_f<<<(OUT_DIM * HID / 4 + 255) / 256, 256>>>(W_fc, (__half*)p_wfcf, OUT_DIM * HID / 4);
    k_gather_split<<<SEQ * BATCH, 256>>>(emb);

    // xh = embf @ wihf^T + b_ih + b_hh : fp16 2-term (B wraps), M=8192, N=1024
    {
        int mblocks = (SEQ * BATCH) / BM;   // 64
        int nblocks = HID / BN;             // 8
        gemm_tc<true><<<mblocks * nblocks, 128, SMEM_TC>>>(
            (const char*)p_embf, (const char*)p_wihf, p_xh, b_ih, b_hh,
            mblocks, HID, 2, KE, HID, KE / BKK, 31);
    }

    // recurrence: persistent HMMA kernel (writes final hidden to out tail)
    k_rnn_persist<<<RNN_BLOCKS, 256, SMEM_RNN>>>(out);

    // outputs = hallf @ wfcf^T + b_fc : fp16 1-term, M=8192, N=32000, K=1024
    {
        int mblocks = (SEQ * BATCH) / BM;   // 64
        int nblocks = OUT_DIM / BN;         // 250
        gemm_tc<true><<<mblocks * nblocks, 128, SMEM_TC>>>(
            (const char*)p_hallf, (const char*)p_wfcf, out, b_fc, nullptr,
            mblocks, OUT_DIM, 1, KF1, HID, KF1 / BKK, 0xFF);
    }
}